// round 9
// baseline (speedup 1.0000x reference)
#include <cuda_runtime.h>
#include <stdint.h>

#define NB    8
#define NMEL  80
#define NT    512
#define NF    401
#define NFFT  800
#define LOUT  102200
#define LPAD  103000
#define ROWS  4096
#define NTOT  1642496     /* ROWS*NF  */
#define FRTOT 3276800     /* ROWS*NFFT */
#define FRB   4           /* frames per chunk in CT kernels */
#define NCHUNK (ROWS/FRB)
#define GRID_CT 512       /* one full wave; each block loops 2 chunks */
#define KPAD  416         /* padded k extent: 32*13 */
#define BW    24          /* mel filter band width (max ~22 nonzeros) */
#define MROWS 8           /* rows per block in mega-mel */

// ------------------------- device scratch (no allocs) ------------------------
__device__ float  g_fb  [NF*NMEL];
__device__ float  g_fbT [NMEL*NF];
__device__ float  g_win [NFFT];
__device__ double g_twcD[NFFT];
__device__ double g_twsD[NFFT];
__device__ float  g_wsqi[LPAD];
__device__ float  g_TIc [25][KPAD];  // (w_k/800)cos(2pi k q/800), 0 for k>=401
__device__ float  g_TIs [25][KPAD];
__device__ float  g_TFc [25][KPAD];  // cos(2pi k q/800)
__device__ float  g_TFs [25][KPAD];
__device__ float  g_c32 [32][17];
__device__ float  g_s32 [32][17];
__device__ int    g_klo [NMEL];      // first nonzero k of fb column m
__device__ float  g_fbc [NMEL][BW];  // fb[klo+j][m], zero-padded
__device__ int    g_ms  [NF];        // first nonzero m of fbT column f
__device__ float  g_fbv [NF][4];     // fbT[ms+j][f], zero-padded
__device__ float  g_spec[NTOT];
__device__ float  g_mag [NTOT];
__device__ float  g_angR[NTOT];
__device__ float  g_angI[NTOT];
__device__ float  g_tR  [NTOT];
__device__ float  g_tI  [NTOT];
__device__ float  g_fr  [FRTOT];
__device__ float  g_inv [NB*LOUT];
__device__ float  g_peak[NB];

// ------------------------- threefry-2x32 (JAX schedule) ----------------------
__host__ __device__ inline void tf_block(unsigned k0, unsigned k1,
                                         unsigned c0, unsigned c1,
                                         unsigned &o0, unsigned &o1){
  unsigned ks2 = k0 ^ k1 ^ 0x1BD11BDAu;
  unsigned x0 = c0 + k0, x1 = c1 + k1;
#define TFR(r) { x0 += x1; x1 = (x1 << (r)) | (x1 >> (32 - (r))); x1 ^= x0; }
  TFR(13) TFR(15) TFR(26) TFR(6)  x0 += k1;  x1 += ks2 + 1u;
  TFR(17) TFR(29) TFR(16) TFR(24) x0 += ks2; x1 += k0 + 2u;
  TFR(13) TFR(15) TFR(26) TFR(6)  x0 += k0;  x1 += k1 + 3u;
  TFR(17) TFR(29) TFR(16) TFR(24) x0 += k1;  x1 += ks2 + 4u;
  TFR(13) TFR(15) TFR(26) TFR(6)  x0 += ks2; x1 += k0 + 5u;
#undef TFR
  o0 = x0; o1 = x1;
}

__device__ __forceinline__ float u01(unsigned bits){
  return __uint_as_float((bits >> 9) | 0x3f800000u) - 1.0f;
}

// ------------------------- setup kernels ------------------------------------
__global__ void k_setup1(){
  int i = blockIdx.x*blockDim.x + threadIdx.x;
  if (i < NFFT){
    g_win[i]  = (float)(0.5 - 0.5*cospi((double)i/400.0));
    g_twcD[i] = cospi((double)i/400.0);
    g_twsD[i] = sinpi((double)i/400.0);
  }
  if (i < NF*NMEL){
    int f = i / NMEL, m = i - f*NMEL;
    double freq = 10.0 * f;
    double mmax = 2595.0 * log10(1.0 + 4000.0/700.0);
    double p0 = 700.0*(pow(10.0, (mmax*(double)(m  )/81.0)/2595.0) - 1.0);
    double p1 = 700.0*(pow(10.0, (mmax*(double)(m+1)/81.0)/2595.0) - 1.0);
    double p2 = 700.0*(pow(10.0, (mmax*(double)(m+2)/81.0)/2595.0) - 1.0);
    double down = (freq - p0) / (p1 - p0);
    double up   = (p2 - freq) / (p2 - p1);
    double v = fmax(0.0, fmin(down, up));
    g_fb [f*NMEL + m] = (float)v;
    g_fbT[m*NF  + f] = (float)v;
  }
}

#define SET2_TOT (LPAD + 25*KPAD + 32*17 + NMEL + NF)
__global__ void k_setup2(){
  int i = blockIdx.x*blockDim.x + threadIdx.x;
  if (i < LPAD){
    int j = i;
    int tlo = (j >= 600) ? (j-600)/200 : 0;
    int thi = j/200; if (thi > 511) thi = 511;
    double s = 0.0;
    for (int t = tlo; t <= thi; t++){
      double w = (double)g_win[j - 200*t];
      s += w*w;
    }
    s = fmax(s, 1e-11);
    g_wsqi[j] = (float)(1.0 / s);
    return;
  }
  int ib = i - LPAD;
  if (ib < 25*KPAD){
    int q = ib / KPAD, k = ib - q*KPAD;
    if (k < NF){
      int r = (k*q) % 800;
      double c = g_twcD[r], s = g_twsD[r];
      double w = (k == 0 || k == 400) ? 1.0 : 2.0;
      g_TIc[q][k] = (float)(w/800.0 * c);
      g_TIs[q][k] = (float)(w/800.0 * s);
      g_TFc[q][k] = (float)c;
      g_TFs[q][k] = (float)s;
    } else {
      g_TIc[q][k] = 0.f; g_TIs[q][k] = 0.f;
      g_TFc[q][k] = 0.f; g_TFs[q][k] = 0.f;
    }
    return;
  }
  int ic = ib - 25*KPAD;
  if (ic < 32*17){
    int a = ic / 17, b = ic - 17*a;
    int r = (a*b) % 32;
    g_c32[a][b] = (float)cospi((double)r/16.0);
    g_s32[a][b] = (float)sinpi((double)r/16.0);
    return;
  }
  int id = ic - 32*17;
  if (id < NMEL){
    int m = id;
    int klo = 0;
    for (int k = 0; k < NF; k++)
      if (g_fb[k*NMEL + m] > 0.f){ klo = k; break; }
    g_klo[m] = klo;
    for (int j = 0; j < BW; j++){
      int k = klo + j;
      g_fbc[m][j] = (k < NF) ? g_fb[k*NMEL + m] : 0.f;
    }
    return;
  }
  int ie = id - NMEL;
  if (ie < NF){
    int f = ie;
    int ms = 0;
    for (int m = 0; m < NMEL; m++)
      if (g_fbT[m*NF + f] > 0.f){ ms = m; break; }
    g_ms[f] = ms;
    for (int j = 0; j < 4; j++){
      int m = ms + j;
      g_fbv[f][j] = (m < NMEL) ? g_fbT[m*NF + f] : 0.f;
    }
  }
}

// ------------------------- RNG init ------------------------------------------
__global__ void k_init(unsigned a0, unsigned a1, unsigned r0, unsigned r1,
                       unsigned q0, unsigned q1){
  int i = blockIdx.x*blockDim.x + threadIdx.x;
  if (i >= NTOT) return;
  unsigned o0, o1;
  tf_block(a0, a1, 0u, (unsigned)i, o0, o1);
  g_spec[i] = u01(o0 ^ o1);                     // spec0 is (B,T,F) = our layout
  g_tR[i] = 0.f; g_tI[i] = 0.f;
  // angles drawn in (B,F,T) order -> remap flat index
  int b = i / (NT*NF);
  int rem = i - b*(NT*NF);
  int t = rem / NF, f = rem - t*NF;
  unsigned j = (unsigned)(b*(NF*NT) + f*NT + t);
  tf_block(r0, r1, 0u, j, o0, o1); g_angR[i] = u01(o0 ^ o1);
  tf_block(q0, q1, 0u, j, o0, o1); g_angI[i] = u01(o0 ^ o1);
}

// ------------------------- mega mel: all 50 SGD iterations in one launch ----
// 256 threads (crossbar-bound; more warps regress). Identical fmaf chains.
struct MelS {
  float sS[MROWS][440];   // spec rows, zero-padded k>=401
  float vS[MROWS][404];   // velocity
  float dS[MROWS][84];    // diff, zero-padded m>=80
  float xS[MROWS][80];    // mel target (cached)
  float fbc[NMEL][BW];
  float fbv[NF][4];
  int   klo[NMEL];
  int   ms[NF];
};

__global__ __launch_bounds__(256)
void k_mel50(const float* __restrict__ x){
  extern __shared__ char smraw[];
  MelS* S = (MelS*)smraw;
  const int tid = threadIdx.x;
  const int row0 = blockIdx.x * MROWS;

  for (int i = tid; i < MROWS*440; i += 256){
    int r = i / 440, k = i - r*440;
    S->sS[r][k] = (k < NF) ? g_spec[(row0 + r)*NF + k] : 0.f;
  }
  for (int i = tid; i < MROWS*404; i += 256){
    int r = i / 404, k = i - r*404;
    S->vS[r][k] = 0.f;
  }
  for (int i = tid; i < MROWS*84; i += 256){
    int r = i / 84, m = i - r*84;
    if (m >= NMEL) S->dS[r][m] = 0.f;
  }
  for (int i = tid; i < MROWS*NMEL; i += 256){
    int r = i / NMEL, m = i - r*NMEL;
    int row = row0 + r, b = row >> 9, t = row & 511;
    S->xS[r][m] = x[(b*NMEL + m)*NT + t];
  }
  for (int i = tid; i < NMEL*BW; i += 256){
    int m = i / BW, j = i - m*BW;
    S->fbc[m][j] = g_fbc[m][j];
  }
  for (int i = tid; i < NF*4; i += 256)
    S->fbv[i >> 2][i & 3] = g_fbv[i >> 2][i & 3];
  for (int i = tid; i < NMEL; i += 256) S->klo[i] = g_klo[i];
  for (int i = tid; i < NF;   i += 256) S->ms[i]  = g_ms[i];
  __syncthreads();

#pragma unroll 1
  for (int it = 0; it < 50; it++){
    // phase A: diff[r][m] = mel_t - sum_k spec*fb (banded, ascending k)
    for (int i = tid; i < MROWS*NMEL; i += 256){
      int r = i / NMEL, m = i - r*NMEL;
      int klo = S->klo[m];
      float acc = 0.f;
#pragma unroll
      for (int j = 0; j < BW; j++)
        acc = fmaf(S->sS[r][klo + j], S->fbc[m][j], acc);
      S->dS[r][m] = S->xS[r][m] - acc;
    }
    __syncthreads();
    // phase B: g = diff@fbT (banded, ascending m) + momentum + clamp
    for (int i = tid; i < MROWS*NF; i += 256){
      int r = i / NF, f = i - r*NF;
      int ms = S->ms[f];
      float acc = 0.f;
#pragma unroll
      for (int j = 0; j < 4; j++)
        acc = fmaf(S->dS[r][ms + j], S->fbv[f][j], acc);
      float g = -0.003125f * acc;             // -2/(B*M)
      float v = 0.9f * S->vS[r][f] + g;
      S->vS[r][f] = v;
      S->sS[r][f] = fmaxf(S->sS[r][f] - 0.1f*v, 0.f);
    }
    __syncthreads();
  }

  // epilogue: mag = sqrt(spec)  (k_mag fused)
  for (int i = tid; i < MROWS*NF; i += 256){
    int r = i / NF, k = i - r*NF;
    g_mag[(row0 + r)*NF + k] = sqrtf(S->sS[r][k]);
  }
}

// ------------------------- CT istft (persistent-lite chunk loop) -------------
struct IstftS {
  union {
    struct { float Pre[FRB][KPAD], Pim[FRB][KPAD]; } a;
    struct { float Aa[FRB][17][25], Bb[FRB][17][25]; } b;
  } u;
  float Hr[FRB][25][32], Hi[FRB][25][32];
  float c32[32][17], s32[32][17];
  float win[NFFT];
};

__global__ __launch_bounds__(256)
void k_istft(){
  __shared__ IstftS S;
  const int tid = threadIdx.x;

  // block-lifetime tables, loaded once
  for (int i = tid; i < 32*17; i += 256){
    int a = i/17, b = i - 17*a;
    S.c32[a][b] = g_c32[a][b]; S.s32[a][b] = g_s32[a][b];
  }
  for (int i = tid; i < NFFT; i += 256) S.win[i] = g_win[i];
  __syncthreads();

#pragma unroll 1
  for (int c = blockIdx.x; c < NCHUNK; c += GRID_CT){
    const int r0 = c * FRB;

    for (int i = tid; i < FRB*KPAD; i += 256){
      int f = i / KPAD, k = i - f*KPAD;
      if (k < NF){
        int idx = (r0 + f)*NF + k;
        float m = g_mag[idx];
        S.u.a.Pre[f][k] = m * g_angR[idx];
        S.u.a.Pim[f][k] = m * g_angI[idx];
      } else { S.u.a.Pre[f][k] = 0.f; S.u.a.Pim[f][k] = 0.f; }
    }
    __syncthreads();

    // stage I1: H[q][m] = sum_{k==m mod 32} T[q][k]*P[k]  (k ascending)
    for (int i = tid; i < 25*32; i += 256){
      int q = i >> 5, m = i & 31;
      float hr[FRB], hi[FRB];
#pragma unroll
      for (int f = 0; f < FRB; f++){ hr[f] = 0.f; hi[f] = 0.f; }
#pragma unroll
      for (int j = 0; j < 13; j++){
        int k = m + (j << 5);
        float tr = g_TIc[q][k], ti = g_TIs[q][k];
#pragma unroll
        for (int f = 0; f < FRB; f++){
          float pr = S.u.a.Pre[f][k], pi = S.u.a.Pim[f][k];
          hr[f] = fmaf(tr, pr, hr[f]); hr[f] = fmaf(-ti, pi, hr[f]);
          hi[f] = fmaf(tr, pi, hi[f]); hi[f] = fmaf( ti, pr, hi[f]);
        }
      }
#pragma unroll
      for (int f = 0; f < FRB; f++){
        S.Hr[f][q][m] = hr[f]; S.Hi[f][q][m] = hi[f];
      }
    }
    __syncthreads();

    // fold m <-> 32-m (real extraction); overlays dead Pre/Pim
    for (int i = tid; i < FRB*17*25; i += 256){
      int f = i / 425, rem = i - f*425;
      int m = rem / 25, q = rem - 25*m;
      float a, b;
      if (m == 0)      { a = S.Hr[f][q][0];  b = 0.f; }
      else if (m == 16){ a = S.Hr[f][q][16]; b = 0.f; }
      else { a = S.Hr[f][q][m] + S.Hr[f][q][32-m];
             b = S.Hi[f][q][32-m] - S.Hi[f][q][m]; }
      S.u.b.Aa[f][m][q] = a; S.u.b.Bb[f][m][q] = b;
    }
    __syncthreads();

    // stage I2 + window
    for (int i = tid; i < FRB*NFFT; i += 256){
      int f = i / NFFT, n = i - f*NFFT;
      int p = n / 25, q = n - 25*p;
      float xv = 0.f;
#pragma unroll
      for (int m = 0; m <= 16; m++){
        xv = fmaf(S.u.b.Aa[f][m][q], S.c32[p][m], xv);
        xv = fmaf(S.u.b.Bb[f][m][q], S.s32[p][m], xv);
      }
      g_fr[(r0 + f)*NFFT + n] = xv * S.win[n];
    }
    __syncthreads();   // protect union: next chunk's Pre/Pim write vs I2 reads
  }
}

// ------------------------- CT stft + GL update (persistent-lite) -------------
struct StftS {
  float fS[FRB][NFFT];
  union {
    struct { float uS[FRB][17][25]; float vS[FRB][17][25]; } fd;
  } u;
  float Gr[FRB][25][17], Gi[FRB][25][17];
  float c32[32][17], s32[32][17];
};

__global__ __launch_bounds__(256)
void k_stft(){
  __shared__ StftS S;
  const int tid = threadIdx.x;

  for (int i = tid; i < 32*17; i += 256){
    int a = i/17, c = i - 17*a;
    S.c32[a][c] = g_c32[a][c]; S.s32[a][c] = g_s32[a][c];
  }

#pragma unroll 1
  for (int c = blockIdx.x; c < NCHUNK; c += GRID_CT){
    const int r0 = c * FRB;

    // reflect-pad gather * window
    for (int i = tid; i < FRB*NFFT; i += 256){
      int f = i / NFFT, n = i - f*NFFT;
      int r = r0 + f, b = r >> 9, t = r & 511;
      int s = t*200 + n - 400;
      if (s < 0) s = -s;
      else if (s >= LOUT) s = 2*LOUT - 2 - s;
      S.fS[f][n] = g_inv[b*LOUT + s] * g_win[n];
    }
    __syncthreads();   // also orders vs previous chunk's F1 (u.fd reads)

    // fold p <-> 32-p (real input)
    for (int i = tid; i < FRB*17*25; i += 256){
      int f = i / 425, rem = i - f*425;
      int p = rem / 25, q = rem - 25*p;
      float u, v;
      if (p == 0)      { u = S.fS[f][q];       v = 0.f; }
      else if (p == 16){ u = S.fS[f][400 + q]; v = 0.f; }
      else { float a = S.fS[f][25*p + q], cc = S.fS[f][25*(32-p) + q];
             u = a + cc; v = a - cc; }
      S.u.fd.uS[f][p][q] = u; S.u.fd.vS[f][p][q] = v;
    }
    __syncthreads();

    // stage F1
    for (int i = tid; i < FRB*25*17; i += 256){
      int f = i / 425, rem = i - f*425;
      int q = rem / 17, m = rem - 17*q;
      float gr = 0.f, gi = 0.f;
#pragma unroll
      for (int p = 0; p <= 16; p++){
        gr = fmaf(S.u.fd.uS[f][p][q], S.c32[m][p], gr);
        gi = fmaf(S.u.fd.vS[f][p][q], S.s32[m][p], gi);
      }
      S.Gr[f][q][m] = gr; S.Gi[f][q][m] = -gi;
    }
    __syncthreads();

    // stage F2 + momentum + phase normalize
    for (int k = tid; k < NF; k += 256){
      int m = k & 31;
      int mm = (m <= 16) ? m : 32 - m;
      float sg = (m <= 16) ? 1.f : -1.f;
      float xr[FRB], xi[FRB];
#pragma unroll
      for (int f = 0; f < FRB; f++){ xr[f] = 0.f; xi[f] = 0.f; }
#pragma unroll 5
      for (int q = 0; q < 25; q++){
        float cc = g_TFc[q][k], s = g_TFs[q][k];
#pragma unroll
        for (int f = 0; f < FRB; f++){
          float grv = S.Gr[f][q][mm], giv = sg*S.Gi[f][q][mm];
          xr[f] = fmaf(cc, grv, xr[f]); xr[f] = fmaf(s, giv, xr[f]);
          xi[f] = fmaf(cc, giv, xi[f]); xi[f] = fmaf(-s, grv, xi[f]);
        }
      }
#pragma unroll
      for (int f = 0; f < FRB; f++){
        int idx = (r0 + f)*NF + k;
        float nR = xr[f] - 0.49748743718592965f * g_tR[idx];   // 0.99/1.99
        float nI = xi[f] - 0.49748743718592965f * g_tI[idx];
        float d = sqrtf(nR*nR + nI*nI) + 1e-16f;
        g_angR[idx] = nR / d;
        g_angI[idx] = nI / d;
        g_tR[idx] = xr[f]; g_tI[idx] = xi[f];
      }
    }
    __syncthreads();   // Gr/Gi reads done before next chunk's F1 writes
  }
}

// ------------------------- elementwise kernels -------------------------------
__global__ void k_ola(){
  int i = blockIdx.x*blockDim.x + threadIdx.x;
  if (i >= NB*LOUT) return;
  int b = i / LOUT, l = i - b*LOUT;
  int j = l + 400;
  int tlo = (j >= 600) ? (j-600)/200 : 0;
  int thi = j/200; if (thi > 511) thi = 511;
  float s = 0.f;
  for (int t = tlo; t <= thi; t++)
    s += g_fr[(b*NT + t)*NFFT + (j - 200*t)];
  g_inv[i] = s * g_wsqi[j];
}

__global__ void k_peak(){
  __shared__ float sm[256];
  int b = blockIdx.x;
  float mx = 0.f;
  for (int l = threadIdx.x; l < LOUT; l += 256)
    mx = fmaxf(mx, fabsf(g_inv[b*LOUT + l]));
  sm[threadIdx.x] = mx;
  __syncthreads();
  for (int s = 128; s > 0; s >>= 1){
    if (threadIdx.x < s) sm[threadIdx.x] = fmaxf(sm[threadIdx.x], sm[threadIdx.x + s]);
    __syncthreads();
  }
  if (threadIdx.x == 0) g_peak[b] = 0.98855309465693896f / sm[0];  // 10^(-0.1/20)
}

__global__ void k_scale(float* __restrict__ out){
  int i = blockIdx.x*blockDim.x + threadIdx.x;
  if (i >= NB*LOUT) return;
  out[i] = g_inv[i] * g_peak[i / LOUT];
}

// ------------------------- host driver ---------------------------------------
extern "C" void kernel_launch(void* const* d_in, const int* in_sizes, int n_in,
                              void* d_out, int out_size){
  const float* x = (const float*)d_in[0];
  float* out = (float*)d_out;

  static int attr_done = 0;
  if (!attr_done){
    cudaFuncSetAttribute(k_mel50, cudaFuncAttributeMaxDynamicSharedMemorySize,
                         (int)sizeof(MelS));
    attr_done = 1;
  }

  // JAX key derivation: key(1)=(0,1); partitionable split -> child_i = block(key,(0,i))
  unsigned a0,a1,b0,b1,r0,r1,q0,q1;
  tf_block(0u,1u, 0u,0u, a0,a1);   // k1  (inverse mel spec0)
  tf_block(0u,1u, 0u,1u, b0,b1);   // k2  (griffin-lim)
  tf_block(b0,b1, 0u,0u, r0,r1);   // kr  (angle real)
  tf_block(b0,b1, 0u,1u, q0,q1);   // ki  (angle imag)

  k_setup1<<<(NF*NMEL + 255)/256, 256>>>();
  k_setup2<<<(SET2_TOT + 255)/256, 256>>>();
  k_init<<<(NTOT + 255)/256, 256>>>(a0,a1,r0,r1,q0,q1);

  // InverseMelScale: all 50 SGD+momentum iterations in ONE launch
  k_mel50<<<ROWS/MROWS, 256, sizeof(MelS)>>>(x);

  // Griffin-Lim: 30 iterations; CT kernels run one full wave each
  for (int it = 0; it < 30; it++){
    k_istft<<<GRID_CT, 256>>>();
    k_ola<<<(NB*LOUT + 255)/256, 256>>>();
    k_stft<<<GRID_CT, 256>>>();
  }

  // final istft with converged phases
  k_istft<<<GRID_CT, 256>>>();
  k_ola<<<(NB*LOUT + 255)/256, 256>>>();

  // normalize to -0.1 dB peak
  k_peak <<<NB, 256>>>();
  k_scale<<<(NB*LOUT + 255)/256, 256>>>(out);
}

// round 10
// speedup vs baseline: 1.0809x; 1.0809x over previous
#include <cuda_runtime.h>
#include <stdint.h>

#define NB    8
#define NMEL  80
#define NT    512
#define NF    401
#define NFFT  800
#define LOUT  102200
#define LPAD  103000
#define ROWS  4096
#define NTOT  1642496     /* ROWS*NF  */
#define FRTOT 3276800     /* ROWS*NFFT */
#define FRB   4           /* frames per block in CT kernels */
#define KPAD  416         /* padded k extent: 32*13 */
#define BW    24          /* mel filter band width (max ~22 nonzeros) */
#define MROWS 8           /* rows per block in mega-mel */

// ------------------------- device scratch (no allocs) ------------------------
__device__ float  g_fb  [NF*NMEL];
__device__ float  g_fbT [NMEL*NF];
__device__ float  g_win [NFFT];
__device__ double g_twcD[NFFT];
__device__ double g_twsD[NFFT];
__device__ float  g_wsqi[LPAD];
__device__ float  g_TIc [25][KPAD];  // (w_k/800)cos(2pi k q/800), 0 for k>=401
__device__ float  g_TIs [25][KPAD];
__device__ float  g_TFc [25][KPAD];  // cos(2pi k q/800)
__device__ float  g_TFs [25][KPAD];
__device__ float  g_c32 [32][17];
__device__ float  g_s32 [32][17];
__device__ int    g_klo [NMEL];      // first nonzero k of fb column m
__device__ float  g_fbc [NMEL][BW];  // fb[klo+j][m], zero-padded
__device__ int    g_ms  [NF];        // first nonzero m of fbT column f
__device__ float  g_fbv [NF][4];     // fbT[ms+j][f], zero-padded
__device__ float  g_spec[NTOT];
__device__ float  g_mag [NTOT];
__device__ float  g_angR[NTOT];
__device__ float  g_angI[NTOT];
__device__ float  g_tR  [NTOT];
__device__ float  g_tI  [NTOT];
__device__ float  g_fr  [FRTOT];
__device__ float  g_inv [NB*LOUT];
__device__ float  g_peak[NB];

// ------------------------- threefry-2x32 (JAX schedule) ----------------------
__host__ __device__ inline void tf_block(unsigned k0, unsigned k1,
                                         unsigned c0, unsigned c1,
                                         unsigned &o0, unsigned &o1){
  unsigned ks2 = k0 ^ k1 ^ 0x1BD11BDAu;
  unsigned x0 = c0 + k0, x1 = c1 + k1;
#define TFR(r) { x0 += x1; x1 = (x1 << (r)) | (x1 >> (32 - (r))); x1 ^= x0; }
  TFR(13) TFR(15) TFR(26) TFR(6)  x0 += k1;  x1 += ks2 + 1u;
  TFR(17) TFR(29) TFR(16) TFR(24) x0 += ks2; x1 += k0 + 2u;
  TFR(13) TFR(15) TFR(26) TFR(6)  x0 += k0;  x1 += k1 + 3u;
  TFR(17) TFR(29) TFR(16) TFR(24) x0 += k1;  x1 += ks2 + 4u;
  TFR(13) TFR(15) TFR(26) TFR(6)  x0 += ks2; x1 += k0 + 5u;
#undef TFR
  o0 = x0; o1 = x1;
}

__device__ __forceinline__ float u01(unsigned bits){
  return __uint_as_float((bits >> 9) | 0x3f800000u) - 1.0f;
}

// ------------------------- setup kernels ------------------------------------
__global__ void k_setup1(){
  int i = blockIdx.x*blockDim.x + threadIdx.x;
  if (i < NFFT){
    g_win[i]  = (float)(0.5 - 0.5*cospi((double)i/400.0));
    g_twcD[i] = cospi((double)i/400.0);
    g_twsD[i] = sinpi((double)i/400.0);
  }
  if (i < NF*NMEL){
    int f = i / NMEL, m = i - f*NMEL;
    double freq = 10.0 * f;
    double mmax = 2595.0 * log10(1.0 + 4000.0/700.0);
    double p0 = 700.0*(pow(10.0, (mmax*(double)(m  )/81.0)/2595.0) - 1.0);
    double p1 = 700.0*(pow(10.0, (mmax*(double)(m+1)/81.0)/2595.0) - 1.0);
    double p2 = 700.0*(pow(10.0, (mmax*(double)(m+2)/81.0)/2595.0) - 1.0);
    double down = (freq - p0) / (p1 - p0);
    double up   = (p2 - freq) / (p2 - p1);
    double v = fmax(0.0, fmin(down, up));
    g_fb [f*NMEL + m] = (float)v;
    g_fbT[m*NF  + f] = (float)v;
  }
}

#define SET2_TOT (LPAD + 25*KPAD + 32*17 + NMEL + NF)
__global__ void k_setup2(){
  int i = blockIdx.x*blockDim.x + threadIdx.x;
  if (i < LPAD){
    int j = i;
    int tlo = (j >= 600) ? (j-600)/200 : 0;
    int thi = j/200; if (thi > 511) thi = 511;
    double s = 0.0;
    for (int t = tlo; t <= thi; t++){
      double w = (double)g_win[j - 200*t];
      s += w*w;
    }
    s = fmax(s, 1e-11);
    g_wsqi[j] = (float)(1.0 / s);
    return;
  }
  int ib = i - LPAD;
  if (ib < 25*KPAD){
    int q = ib / KPAD, k = ib - q*KPAD;
    if (k < NF){
      int r = (k*q) % 800;
      double c = g_twcD[r], s = g_twsD[r];
      double w = (k == 0 || k == 400) ? 1.0 : 2.0;
      g_TIc[q][k] = (float)(w/800.0 * c);
      g_TIs[q][k] = (float)(w/800.0 * s);
      g_TFc[q][k] = (float)c;
      g_TFs[q][k] = (float)s;
    } else {
      g_TIc[q][k] = 0.f; g_TIs[q][k] = 0.f;
      g_TFc[q][k] = 0.f; g_TFs[q][k] = 0.f;
    }
    return;
  }
  int ic = ib - 25*KPAD;
  if (ic < 32*17){
    int a = ic / 17, b = ic - 17*a;
    int r = (a*b) % 32;
    g_c32[a][b] = (float)cospi((double)r/16.0);
    g_s32[a][b] = (float)sinpi((double)r/16.0);
    return;
  }
  int id = ic - 32*17;
  if (id < NMEL){
    int m = id;
    int klo = 0;
    for (int k = 0; k < NF; k++)
      if (g_fb[k*NMEL + m] > 0.f){ klo = k; break; }
    g_klo[m] = klo;
    for (int j = 0; j < BW; j++){
      int k = klo + j;
      g_fbc[m][j] = (k < NF) ? g_fb[k*NMEL + m] : 0.f;
    }
    return;
  }
  int ie = id - NMEL;
  if (ie < NF){
    int f = ie;
    int ms = 0;
    for (int m = 0; m < NMEL; m++)
      if (g_fbT[m*NF + f] > 0.f){ ms = m; break; }
    g_ms[f] = ms;
    for (int j = 0; j < 4; j++){
      int m = ms + j;
      g_fbv[f][j] = (m < NMEL) ? g_fbT[m*NF + f] : 0.f;
    }
  }
}

// ------------------------- RNG init ------------------------------------------
__global__ void k_init(unsigned a0, unsigned a1, unsigned r0, unsigned r1,
                       unsigned q0, unsigned q1){
  int i = blockIdx.x*blockDim.x + threadIdx.x;
  if (i >= NTOT) return;
  unsigned o0, o1;
  tf_block(a0, a1, 0u, (unsigned)i, o0, o1);
  g_spec[i] = u01(o0 ^ o1);                     // spec0 is (B,T,F) = our layout
  g_tR[i] = 0.f; g_tI[i] = 0.f;
  // angles drawn in (B,F,T) order -> remap flat index
  int b = i / (NT*NF);
  int rem = i - b*(NT*NF);
  int t = rem / NF, f = rem - t*NF;
  unsigned j = (unsigned)(b*(NF*NT) + f*NT + t);
  tf_block(r0, r1, 0u, j, o0, o1); g_angR[i] = u01(o0 ^ o1);
  tf_block(q0, q1, 0u, j, o0, o1); g_angI[i] = u01(o0 ^ o1);
}

// ------------------------- mega mel: all 50 SGD iterations in one launch ----
// 256 threads (crossbar-bound; more warps regress). Identical fmaf chains.
struct MelS {
  float sS[MROWS][440];   // spec rows, zero-padded k>=401
  float vS[MROWS][404];   // velocity
  float dS[MROWS][84];    // diff, zero-padded m>=80
  float xS[MROWS][80];    // mel target (cached)
  float fbc[NMEL][BW];
  float fbv[NF][4];
  int   klo[NMEL];
  int   ms[NF];
};

__global__ __launch_bounds__(256)
void k_mel50(const float* __restrict__ x){
  extern __shared__ char smraw[];
  MelS* S = (MelS*)smraw;
  const int tid = threadIdx.x;
  const int row0 = blockIdx.x * MROWS;

  for (int i = tid; i < MROWS*440; i += 256){
    int r = i / 440, k = i - r*440;
    S->sS[r][k] = (k < NF) ? g_spec[(row0 + r)*NF + k] : 0.f;
  }
  for (int i = tid; i < MROWS*404; i += 256){
    int r = i / 404, k = i - r*404;
    S->vS[r][k] = 0.f;
  }
  for (int i = tid; i < MROWS*84; i += 256){
    int r = i / 84, m = i - r*84;
    if (m >= NMEL) S->dS[r][m] = 0.f;
  }
  for (int i = tid; i < MROWS*NMEL; i += 256){
    int r = i / NMEL, m = i - r*NMEL;
    int row = row0 + r, b = row >> 9, t = row & 511;
    S->xS[r][m] = x[(b*NMEL + m)*NT + t];
  }
  for (int i = tid; i < NMEL*BW; i += 256){
    int m = i / BW, j = i - m*BW;
    S->fbc[m][j] = g_fbc[m][j];
  }
  for (int i = tid; i < NF*4; i += 256)
    S->fbv[i >> 2][i & 3] = g_fbv[i >> 2][i & 3];
  for (int i = tid; i < NMEL; i += 256) S->klo[i] = g_klo[i];
  for (int i = tid; i < NF;   i += 256) S->ms[i]  = g_ms[i];
  __syncthreads();

#pragma unroll 1
  for (int it = 0; it < 50; it++){
    // phase A: diff[r][m] = mel_t - sum_k spec*fb (banded, ascending k)
    for (int i = tid; i < MROWS*NMEL; i += 256){
      int r = i / NMEL, m = i - r*NMEL;
      int klo = S->klo[m];
      float acc = 0.f;
#pragma unroll
      for (int j = 0; j < BW; j++)
        acc = fmaf(S->sS[r][klo + j], S->fbc[m][j], acc);
      S->dS[r][m] = S->xS[r][m] - acc;
    }
    __syncthreads();
    // phase B: g = diff@fbT (banded, ascending m) + momentum + clamp
    for (int i = tid; i < MROWS*NF; i += 256){
      int r = i / NF, f = i - r*NF;
      int ms = S->ms[f];
      float acc = 0.f;
#pragma unroll
      for (int j = 0; j < 4; j++)
        acc = fmaf(S->dS[r][ms + j], S->fbv[f][j], acc);
      float g = -0.003125f * acc;             // -2/(B*M)
      float v = 0.9f * S->vS[r][f] + g;
      S->vS[r][f] = v;
      S->sS[r][f] = fmaxf(S->sS[r][f] - 0.1f*v, 0.f);
    }
    __syncthreads();
  }

  // epilogue: mag = sqrt(spec)  (k_mag fused)
  for (int i = tid; i < MROWS*NF; i += 256){
    int r = i / NF, k = i - r*NF;
    g_mag[(row0 + r)*NF + k] = sqrtf(S->sS[r][k]);
  }
}

// ------------------------- CT istft (fused I1+fold, ~31KB smem) --------------
// Thread computes H[q][m] and H[q][32-m] column sums in registers (identical
// 13-tap ascending-k chains), then combines exactly as the old fold stage.
struct IstftS {
  float Pre[FRB][KPAD], Pim[FRB][KPAD];     // 13.3 KB
  float Aa[FRB][17][25], Bb[FRB][17][25];   // 13.6 KB
  float c32[32][17], s32[32][17];           //  4.3 KB
};

__global__ __launch_bounds__(256)
void k_istft(){
  __shared__ IstftS S;
  const int tid = threadIdx.x;
  const int r0 = blockIdx.x * FRB;

  for (int i = tid; i < 32*17; i += 256){
    int a = i/17, b = i - 17*a;
    S.c32[a][b] = g_c32[a][b]; S.s32[a][b] = g_s32[a][b];
  }
  for (int i = tid; i < FRB*KPAD; i += 256){
    int f = i / KPAD, k = i - f*KPAD;
    if (k < NF){
      int idx = (r0 + f)*NF + k;
      float m = g_mag[idx];
      S.Pre[f][k] = m * g_angR[idx];
      S.Pim[f][k] = m * g_angI[idx];
    } else { S.Pre[f][k] = 0.f; S.Pim[f][k] = 0.f; }
  }
  __syncthreads();

  // fused I1 + fold: outputs Aa/Bb[f][m][q] for m in 0..16
  for (int i = tid; i < 17*25; i += 256){
    int m = i / 25, q = i - 25*m;
    float hr0[FRB], hi0[FRB];
#pragma unroll
    for (int f = 0; f < FRB; f++){ hr0[f] = 0.f; hi0[f] = 0.f; }
#pragma unroll
    for (int j = 0; j < 13; j++){
      int k = m + (j << 5);
      float tr = g_TIc[q][k], ti = g_TIs[q][k];
#pragma unroll
      for (int f = 0; f < FRB; f++){
        float pr = S.Pre[f][k], pi = S.Pim[f][k];
        hr0[f] = fmaf(tr, pr, hr0[f]); hr0[f] = fmaf(-ti, pi, hr0[f]);
        hi0[f] = fmaf(tr, pi, hi0[f]); hi0[f] = fmaf( ti, pr, hi0[f]);
      }
    }
    if (m == 0 || m == 16){
#pragma unroll
      for (int f = 0; f < FRB; f++){
        S.Aa[f][m][q] = hr0[f]; S.Bb[f][m][q] = 0.f;
      }
    } else {
      int m2 = 32 - m;
      float hr1[FRB], hi1[FRB];
#pragma unroll
      for (int f = 0; f < FRB; f++){ hr1[f] = 0.f; hi1[f] = 0.f; }
#pragma unroll
      for (int j = 0; j < 13; j++){
        int k = m2 + (j << 5);
        float tr = g_TIc[q][k], ti = g_TIs[q][k];
#pragma unroll
        for (int f = 0; f < FRB; f++){
          float pr = S.Pre[f][k], pi = S.Pim[f][k];
          hr1[f] = fmaf(tr, pr, hr1[f]); hr1[f] = fmaf(-ti, pi, hr1[f]);
          hi1[f] = fmaf(tr, pi, hi1[f]); hi1[f] = fmaf( ti, pr, hi1[f]);
        }
      }
#pragma unroll
      for (int f = 0; f < FRB; f++){
        S.Aa[f][m][q] = hr0[f] + hr1[f];
        S.Bb[f][m][q] = hi1[f] - hi0[f];
      }
    }
  }
  __syncthreads();

  // stage I2 + window (win from L1-cached global)
  for (int i = tid; i < FRB*NFFT; i += 256){
    int f = i / NFFT, n = i - f*NFFT;
    int p = n / 25, q = n - 25*p;
    float xv = 0.f;
#pragma unroll
    for (int m = 0; m <= 16; m++){
      xv = fmaf(S.Aa[f][m][q], S.c32[p][m], xv);
      xv = fmaf(S.Bb[f][m][q], S.s32[p][m], xv);
    }
    g_fr[(r0 + f)*NFFT + n] = xv * g_win[n];
  }
}

// ------------------------- CT stft + GL update (Gr/Gi overlays fS) -----------
struct StftS {
  union {
    float fS[FRB][NFFT];                                  // 12.8 KB
    struct { float Gr[FRB][25][17], Gi[FRB][25][17]; } g; // 13.6 KB
  } a;
  float uS[FRB][17][25], vS[FRB][17][25];                 // 13.6 KB
  float c32[32][17], s32[32][17];                         //  4.3 KB
};

__global__ __launch_bounds__(256)
void k_stft(){
  __shared__ StftS S;
  const int tid = threadIdx.x;
  const int r0 = blockIdx.x * FRB;

  for (int i = tid; i < 32*17; i += 256){
    int a = i/17, c = i - 17*a;
    S.c32[a][c] = g_c32[a][c]; S.s32[a][c] = g_s32[a][c];
  }
  // reflect-pad gather * window
  for (int i = tid; i < FRB*NFFT; i += 256){
    int f = i / NFFT, n = i - f*NFFT;
    int r = r0 + f, b = r >> 9, t = r & 511;
    int s = t*200 + n - 400;
    if (s < 0) s = -s;
    else if (s >= LOUT) s = 2*LOUT - 2 - s;
    S.a.fS[f][n] = g_inv[b*LOUT + s] * g_win[n];
  }
  __syncthreads();

  // fold p <-> 32-p (real input)
  for (int i = tid; i < FRB*17*25; i += 256){
    int f = i / 425, rem = i - f*425;
    int p = rem / 25, q = rem - 25*p;
    float u, v;
    if (p == 0)      { u = S.a.fS[f][q];       v = 0.f; }
    else if (p == 16){ u = S.a.fS[f][400 + q]; v = 0.f; }
    else { float a = S.a.fS[f][25*p + q], cc = S.a.fS[f][25*(32-p) + q];
           u = a + cc; v = a - cc; }
    S.uS[f][p][q] = u; S.vS[f][p][q] = v;
  }
  __syncthreads();

  // stage F1 (writes Gr/Gi over dead fS)
  for (int i = tid; i < FRB*25*17; i += 256){
    int f = i / 425, rem = i - f*425;
    int q = rem / 17, m = rem - 17*q;
    float gr = 0.f, gi = 0.f;
#pragma unroll
    for (int p = 0; p <= 16; p++){
      gr = fmaf(S.uS[f][p][q], S.c32[m][p], gr);
      gi = fmaf(S.vS[f][p][q], S.s32[m][p], gi);
    }
    S.a.g.Gr[f][q][m] = gr; S.a.g.Gi[f][q][m] = -gi;
  }
  __syncthreads();

  // stage F2 + momentum + phase normalize
  for (int k = tid; k < NF; k += 256){
    int m = k & 31;
    int mm = (m <= 16) ? m : 32 - m;
    float sg = (m <= 16) ? 1.f : -1.f;
    float xr[FRB], xi[FRB];
#pragma unroll
    for (int f = 0; f < FRB; f++){ xr[f] = 0.f; xi[f] = 0.f; }
#pragma unroll 5
    for (int q = 0; q < 25; q++){
      float cc = g_TFc[q][k], s = g_TFs[q][k];
#pragma unroll
      for (int f = 0; f < FRB; f++){
        float grv = S.a.g.Gr[f][q][mm], giv = sg*S.a.g.Gi[f][q][mm];
        xr[f] = fmaf(cc, grv, xr[f]); xr[f] = fmaf(s, giv, xr[f]);
        xi[f] = fmaf(cc, giv, xi[f]); xi[f] = fmaf(-s, grv, xi[f]);
      }
    }
#pragma unroll
    for (int f = 0; f < FRB; f++){
      int idx = (r0 + f)*NF + k;
      float nR = xr[f] - 0.49748743718592965f * g_tR[idx];   // 0.99/1.99
      float nI = xi[f] - 0.49748743718592965f * g_tI[idx];
      float d = sqrtf(nR*nR + nI*nI) + 1e-16f;
      g_angR[idx] = nR / d;
      g_angI[idx] = nI / d;
      g_tR[idx] = xr[f]; g_tI[idx] = xi[f];
    }
  }
}

// ------------------------- elementwise kernels -------------------------------
__global__ void k_ola(){
  int i = blockIdx.x*blockDim.x + threadIdx.x;
  if (i >= NB*LOUT) return;
  int b = i / LOUT, l = i - b*LOUT;
  int j = l + 400;
  int tlo = (j >= 600) ? (j-600)/200 : 0;
  int thi = j/200; if (thi > 511) thi = 511;
  float s = 0.f;
  for (int t = tlo; t <= thi; t++)
    s += g_fr[(b*NT + t)*NFFT + (j - 200*t)];
  g_inv[i] = s * g_wsqi[j];
}

__global__ void k_peak(){
  __shared__ float sm[256];
  int b = blockIdx.x;
  float mx = 0.f;
  for (int l = threadIdx.x; l < LOUT; l += 256)
    mx = fmaxf(mx, fabsf(g_inv[b*LOUT + l]));
  sm[threadIdx.x] = mx;
  __syncthreads();
  for (int s = 128; s > 0; s >>= 1){
    if (threadIdx.x < s) sm[threadIdx.x] = fmaxf(sm[threadIdx.x], sm[threadIdx.x + s]);
    __syncthreads();
  }
  if (threadIdx.x == 0) g_peak[b] = 0.98855309465693896f / sm[0];  // 10^(-0.1/20)
}

__global__ void k_scale(float* __restrict__ out){
  int i = blockIdx.x*blockDim.x + threadIdx.x;
  if (i >= NB*LOUT) return;
  out[i] = g_inv[i] * g_peak[i / LOUT];
}

// ------------------------- host driver ---------------------------------------
extern "C" void kernel_launch(void* const* d_in, const int* in_sizes, int n_in,
                              void* d_out, int out_size){
  const float* x = (const float*)d_in[0];
  float* out = (float*)d_out;

  static int attr_done = 0;
  if (!attr_done){
    cudaFuncSetAttribute(k_mel50, cudaFuncAttributeMaxDynamicSharedMemorySize,
                         (int)sizeof(MelS));
    attr_done = 1;
  }

  // JAX key derivation: key(1)=(0,1); partitionable split -> child_i = block(key,(0,i))
  unsigned a0,a1,b0,b1,r0,r1,q0,q1;
  tf_block(0u,1u, 0u,0u, a0,a1);   // k1  (inverse mel spec0)
  tf_block(0u,1u, 0u,1u, b0,b1);   // k2  (griffin-lim)
  tf_block(b0,b1, 0u,0u, r0,r1);   // kr  (angle real)
  tf_block(b0,b1, 0u,1u, q0,q1);   // ki  (angle imag)

  k_setup1<<<(NF*NMEL + 255)/256, 256>>>();
  k_setup2<<<(SET2_TOT + 255)/256, 256>>>();
  k_init<<<(NTOT + 255)/256, 256>>>(a0,a1,r0,r1,q0,q1);

  // InverseMelScale: all 50 SGD+momentum iterations in ONE launch
  k_mel50<<<ROWS/MROWS, 256, sizeof(MelS)>>>(x);

  // Griffin-Lim: 30 iterations (grid=1024, one chunk per block — R8 shape)
  for (int it = 0; it < 30; it++){
    k_istft<<<ROWS/FRB, 256>>>();
    k_ola<<<(NB*LOUT + 255)/256, 256>>>();
    k_stft<<<ROWS/FRB, 256>>>();
  }

  // final istft with converged phases
  k_istft<<<ROWS/FRB, 256>>>();
  k_ola<<<(NB*LOUT + 255)/256, 256>>>();

  // normalize to -0.1 dB peak
  k_peak <<<NB, 256>>>();
  k_scale<<<(NB*LOUT + 255)/256, 256>>>(out);
}

// round 11
// speedup vs baseline: 1.1906x; 1.1015x over previous
#include <cuda_runtime.h>
#include <stdint.h>

#define NB    8
#define NMEL  80
#define NT    512
#define NF    401
#define NFFT  800
#define LOUT  102200
#define LPAD  103000
#define ROWS  4096
#define NTOT  1642496     /* ROWS*NF  */
#define FRTOT 3276800     /* ROWS*NFFT */
#define FRB   4           /* frames per block in CT kernels */
#define KPAD  416         /* padded k extent: 32*13 */
#define BW    24          /* mel filter band width (max ~22 nonzeros) */
#define MROWS 8           /* rows per block in mega-mel */

// ------------------------- device scratch (no allocs) ------------------------
__device__ float  g_fb  [NF*NMEL];
__device__ float  g_fbT [NMEL*NF];
__device__ float  g_win [NFFT];
__device__ double g_twcD[NFFT];
__device__ double g_twsD[NFFT];
__device__ float  g_wsqi[LPAD];
__device__ float  g_TIc [25][KPAD];  // (w_k/800)cos(2pi k q/800), 0 for k>=401
__device__ float  g_TIs [25][KPAD];
__device__ float  g_TFc [25][KPAD];  // cos(2pi k q/800)
__device__ float  g_TFs [25][KPAD];
__device__ float  g_c32 [32][17];
__device__ float  g_s32 [32][17];
__device__ int    g_klo [NMEL];      // first nonzero k of fb column m
__device__ float  g_fbc [NMEL][BW];  // fb[klo+j][m], zero-padded
__device__ int    g_ms  [NF];        // first nonzero m of fbT column f
__device__ float  g_fbv [NF][4];     // fbT[ms+j][f], zero-padded
__device__ float  g_spec[NTOT];
__device__ float  g_mag [NTOT];
__device__ float  g_angR[NTOT];
__device__ float  g_angI[NTOT];
__device__ float  g_tR  [NTOT];
__device__ float  g_tI  [NTOT];
__device__ float  g_fr  [FRTOT];
__device__ float  g_inv [NB*LOUT];
__device__ float  g_peak[NB];

// ------------------------- threefry-2x32 (JAX schedule) ----------------------
__host__ __device__ inline void tf_block(unsigned k0, unsigned k1,
                                         unsigned c0, unsigned c1,
                                         unsigned &o0, unsigned &o1){
  unsigned ks2 = k0 ^ k1 ^ 0x1BD11BDAu;
  unsigned x0 = c0 + k0, x1 = c1 + k1;
#define TFR(r) { x0 += x1; x1 = (x1 << (r)) | (x1 >> (32 - (r))); x1 ^= x0; }
  TFR(13) TFR(15) TFR(26) TFR(6)  x0 += k1;  x1 += ks2 + 1u;
  TFR(17) TFR(29) TFR(16) TFR(24) x0 += ks2; x1 += k0 + 2u;
  TFR(13) TFR(15) TFR(26) TFR(6)  x0 += k0;  x1 += k1 + 3u;
  TFR(17) TFR(29) TFR(16) TFR(24) x0 += k1;  x1 += ks2 + 4u;
  TFR(13) TFR(15) TFR(26) TFR(6)  x0 += ks2; x1 += k0 + 5u;
#undef TFR
  o0 = x0; o1 = x1;
}

__device__ __forceinline__ float u01(unsigned bits){
  return __uint_as_float((bits >> 9) | 0x3f800000u) - 1.0f;
}

// ------------------------- setup kernels ------------------------------------
__global__ void k_setup1(){
  int i = blockIdx.x*blockDim.x + threadIdx.x;
  if (i < NFFT){
    g_win[i]  = (float)(0.5 - 0.5*cospi((double)i/400.0));
    g_twcD[i] = cospi((double)i/400.0);
    g_twsD[i] = sinpi((double)i/400.0);
  }
  if (i < NF*NMEL){
    int f = i / NMEL, m = i - f*NMEL;
    double freq = 10.0 * f;
    double mmax = 2595.0 * log10(1.0 + 4000.0/700.0);
    double p0 = 700.0*(pow(10.0, (mmax*(double)(m  )/81.0)/2595.0) - 1.0);
    double p1 = 700.0*(pow(10.0, (mmax*(double)(m+1)/81.0)/2595.0) - 1.0);
    double p2 = 700.0*(pow(10.0, (mmax*(double)(m+2)/81.0)/2595.0) - 1.0);
    double down = (freq - p0) / (p1 - p0);
    double up   = (p2 - freq) / (p2 - p1);
    double v = fmax(0.0, fmin(down, up));
    g_fb [f*NMEL + m] = (float)v;
    g_fbT[m*NF  + f] = (float)v;
  }
}

#define SET2_TOT (LPAD + 25*KPAD + 32*17 + NMEL + NF)
__global__ void k_setup2(){
  int i = blockIdx.x*blockDim.x + threadIdx.x;
  if (i < LPAD){
    int j = i;
    int tlo = (j >= 600) ? (j-600)/200 : 0;
    int thi = j/200; if (thi > 511) thi = 511;
    double s = 0.0;
    for (int t = tlo; t <= thi; t++){
      double w = (double)g_win[j - 200*t];
      s += w*w;
    }
    s = fmax(s, 1e-11);
    g_wsqi[j] = (float)(1.0 / s);
    return;
  }
  int ib = i - LPAD;
  if (ib < 25*KPAD){
    int q = ib / KPAD, k = ib - q*KPAD;
    if (k < NF){
      int r = (k*q) % 800;
      double c = g_twcD[r], s = g_twsD[r];
      double w = (k == 0 || k == 400) ? 1.0 : 2.0;
      g_TIc[q][k] = (float)(w/800.0 * c);
      g_TIs[q][k] = (float)(w/800.0 * s);
      g_TFc[q][k] = (float)c;
      g_TFs[q][k] = (float)s;
    } else {
      g_TIc[q][k] = 0.f; g_TIs[q][k] = 0.f;
      g_TFc[q][k] = 0.f; g_TFs[q][k] = 0.f;
    }
    return;
  }
  int ic = ib - 25*KPAD;
  if (ic < 32*17){
    int a = ic / 17, b = ic - 17*a;
    int r = (a*b) % 32;
    g_c32[a][b] = (float)cospi((double)r/16.0);
    g_s32[a][b] = (float)sinpi((double)r/16.0);
    return;
  }
  int id = ic - 32*17;
  if (id < NMEL){
    int m = id;
    int klo = 0;
    for (int k = 0; k < NF; k++)
      if (g_fb[k*NMEL + m] > 0.f){ klo = k; break; }
    g_klo[m] = klo;
    for (int j = 0; j < BW; j++){
      int k = klo + j;
      g_fbc[m][j] = (k < NF) ? g_fb[k*NMEL + m] : 0.f;
    }
    return;
  }
  int ie = id - NMEL;
  if (ie < NF){
    int f = ie;
    int ms = 0;
    for (int m = 0; m < NMEL; m++)
      if (g_fbT[m*NF + f] > 0.f){ ms = m; break; }
    g_ms[f] = ms;
    for (int j = 0; j < 4; j++){
      int m = ms + j;
      g_fbv[f][j] = (m < NMEL) ? g_fbT[m*NF + f] : 0.f;
    }
  }
}

// ------------------------- RNG init ------------------------------------------
__global__ void k_init(unsigned a0, unsigned a1, unsigned r0, unsigned r1,
                       unsigned q0, unsigned q1){
  int i = blockIdx.x*blockDim.x + threadIdx.x;
  if (i >= NTOT) return;
  unsigned o0, o1;
  tf_block(a0, a1, 0u, (unsigned)i, o0, o1);
  g_spec[i] = u01(o0 ^ o1);                     // spec0 is (B,T,F) = our layout
  g_tR[i] = 0.f; g_tI[i] = 0.f;
  // angles drawn in (B,F,T) order -> remap flat index
  int b = i / (NT*NF);
  int rem = i - b*(NT*NF);
  int t = rem / NF, f = rem - t*NF;
  unsigned j = (unsigned)(b*(NF*NT) + f*NT + t);
  tf_block(r0, r1, 0u, j, o0, o1); g_angR[i] = u01(o0 ^ o1);
  tf_block(q0, q1, 0u, j, o0, o1); g_angI[i] = u01(o0 ^ o1);
}

// ------------------------- mega mel: all 50 SGD iterations in one launch ----
// 256 threads; 2 outputs per thread in both phases for ILP.
// Per-output fmaf chains identical to the validated banded version.
struct MelS {
  float sS[MROWS][440];   // spec rows, zero-padded k>=401
  float vS[MROWS][404];   // velocity
  float dS[MROWS][84];    // diff, zero-padded m>=80
  float xS[MROWS][80];    // mel target (cached)
  float fbc[NMEL][BW];
  float fbv[NF][4];
  int   klo[NMEL];
  int   ms[NF];
};

__global__ __launch_bounds__(256)
void k_mel50(const float* __restrict__ x){
  extern __shared__ char smraw[];
  MelS* S = (MelS*)smraw;
  const int tid = threadIdx.x;
  const int row0 = blockIdx.x * MROWS;

  for (int i = tid; i < MROWS*440; i += 256){
    int r = i / 440, k = i - r*440;
    S->sS[r][k] = (k < NF) ? g_spec[(row0 + r)*NF + k] : 0.f;
  }
  for (int i = tid; i < MROWS*404; i += 256){
    int r = i / 404, k = i - r*404;
    S->vS[r][k] = 0.f;
  }
  for (int i = tid; i < MROWS*84; i += 256){
    int r = i / 84, m = i - r*84;
    if (m >= NMEL) S->dS[r][m] = 0.f;
  }
  for (int i = tid; i < MROWS*NMEL; i += 256){
    int r = i / NMEL, m = i - r*NMEL;
    int row = row0 + r, b = row >> 9, t = row & 511;
    S->xS[r][m] = x[(b*NMEL + m)*NT + t];
  }
  for (int i = tid; i < NMEL*BW; i += 256){
    int m = i / BW, j = i - m*BW;
    S->fbc[m][j] = g_fbc[m][j];
  }
  for (int i = tid; i < NF*4; i += 256)
    S->fbv[i >> 2][i & 3] = g_fbv[i >> 2][i & 3];
  for (int i = tid; i < NMEL; i += 256) S->klo[i] = g_klo[i];
  for (int i = tid; i < NF;   i += 256) S->ms[i]  = g_ms[i];
  __syncthreads();

#pragma unroll 1
  for (int it = 0; it < 50; it++){
    // phase A: diff[r][m] = mel_t - sum_k spec*fb  (2 m-outputs per thread)
    for (int i = tid; i < MROWS*40; i += 256){
      int r = i / 40, mp = i - r*40;
      int m0 = mp << 1, m1 = m0 + 1;
      int klo0 = S->klo[m0], klo1 = S->klo[m1];
      float acc0 = 0.f, acc1 = 0.f;
#pragma unroll
      for (int j = 0; j < BW; j++){
        acc0 = fmaf(S->sS[r][klo0 + j], S->fbc[m0][j], acc0);
        acc1 = fmaf(S->sS[r][klo1 + j], S->fbc[m1][j], acc1);
      }
      S->dS[r][m0] = S->xS[r][m0] - acc0;
      S->dS[r][m1] = S->xS[r][m1] - acc1;
    }
    __syncthreads();
    // phase B: g = diff@fbT + momentum + clamp  (2 f-outputs per thread)
    for (int i = tid; i < MROWS*201; i += 256){
      int r = i / 201, fp = i - r*201;
      int f0 = fp << 1, f1 = f0 + 1;
      int ms0 = S->ms[f0];
      float acc0 = 0.f, acc1 = 0.f;
      if (f1 < NF){
        int ms1 = S->ms[f1];
#pragma unroll
        for (int j = 0; j < 4; j++){
          acc0 = fmaf(S->dS[r][ms0 + j], S->fbv[f0][j], acc0);
          acc1 = fmaf(S->dS[r][ms1 + j], S->fbv[f1][j], acc1);
        }
        float g1 = -0.003125f * acc1;
        float v1 = 0.9f * S->vS[r][f1] + g1;
        S->vS[r][f1] = v1;
        S->sS[r][f1] = fmaxf(S->sS[r][f1] - 0.1f*v1, 0.f);
      } else {
#pragma unroll
        for (int j = 0; j < 4; j++)
          acc0 = fmaf(S->dS[r][ms0 + j], S->fbv[f0][j], acc0);
      }
      float g0 = -0.003125f * acc0;
      float v0 = 0.9f * S->vS[r][f0] + g0;
      S->vS[r][f0] = v0;
      S->sS[r][f0] = fmaxf(S->sS[r][f0] - 0.1f*v0, 0.f);
    }
    __syncthreads();
  }

  // epilogue: mag = sqrt(spec)  (k_mag fused)
  for (int i = tid; i < MROWS*NF; i += 256){
    int r = i / NF, k = i - r*NF;
    g_mag[(row0 + r)*NF + k] = sqrtf(S->sS[r][k]);
  }
}

// ------------------------- CT istft (R8 structure, win from global) ----------
struct IstftS {
  union {
    struct { float Pre[FRB][KPAD], Pim[FRB][KPAD]; } a;
    struct { float Aa[FRB][17][25], Bb[FRB][17][25]; } b;
  } u;
  float Hr[FRB][25][32], Hi[FRB][25][32];
  float c32[32][17], s32[32][17];
};

__global__ __launch_bounds__(256)
void k_istft(){
  __shared__ IstftS S;
  const int tid = threadIdx.x;
  const int r0 = blockIdx.x * FRB;

  for (int i = tid; i < 32*17; i += 256){
    int a = i/17, b = i - 17*a;
    S.c32[a][b] = g_c32[a][b]; S.s32[a][b] = g_s32[a][b];
  }
  for (int i = tid; i < FRB*KPAD; i += 256){
    int f = i / KPAD, k = i - f*KPAD;
    if (k < NF){
      int idx = (r0 + f)*NF + k;
      float m = g_mag[idx];
      S.u.a.Pre[f][k] = m * g_angR[idx];
      S.u.a.Pim[f][k] = m * g_angI[idx];
    } else { S.u.a.Pre[f][k] = 0.f; S.u.a.Pim[f][k] = 0.f; }
  }
  __syncthreads();

  // stage I1: H[q][m] = sum_{k==m mod 32} T[q][k]*P[k]  (k ascending)
  for (int i = tid; i < 25*32; i += 256){
    int q = i >> 5, m = i & 31;
    float hr[FRB], hi[FRB];
#pragma unroll
    for (int f = 0; f < FRB; f++){ hr[f] = 0.f; hi[f] = 0.f; }
#pragma unroll
    for (int j = 0; j < 13; j++){
      int k = m + (j << 5);
      float tr = g_TIc[q][k], ti = g_TIs[q][k];
#pragma unroll
      for (int f = 0; f < FRB; f++){
        float pr = S.u.a.Pre[f][k], pi = S.u.a.Pim[f][k];
        hr[f] = fmaf(tr, pr, hr[f]); hr[f] = fmaf(-ti, pi, hr[f]);
        hi[f] = fmaf(tr, pi, hi[f]); hi[f] = fmaf( ti, pr, hi[f]);
      }
    }
#pragma unroll
    for (int f = 0; f < FRB; f++){
      S.Hr[f][q][m] = hr[f]; S.Hi[f][q][m] = hi[f];
    }
  }
  __syncthreads();

  // fold m <-> 32-m (real extraction); overlays dead Pre/Pim
  for (int i = tid; i < FRB*17*25; i += 256){
    int f = i / 425, rem = i - f*425;
    int m = rem / 25, q = rem - 25*m;
    float a, b;
    if (m == 0)      { a = S.Hr[f][q][0];  b = 0.f; }
    else if (m == 16){ a = S.Hr[f][q][16]; b = 0.f; }
    else { a = S.Hr[f][q][m] + S.Hr[f][q][32-m];
           b = S.Hi[f][q][32-m] - S.Hi[f][q][m]; }
    S.u.b.Aa[f][m][q] = a; S.u.b.Bb[f][m][q] = b;
  }
  __syncthreads();

  // stage I2 + window (win via L1-cached global read)
  for (int i = tid; i < FRB*NFFT; i += 256){
    int f = i / NFFT, n = i - f*NFFT;
    int p = n / 25, q = n - 25*p;
    float xv = 0.f;
#pragma unroll
    for (int m = 0; m <= 16; m++){
      xv = fmaf(S.u.b.Aa[f][m][q], S.c32[p][m], xv);
      xv = fmaf(S.u.b.Bb[f][m][q], S.s32[p][m], xv);
    }
    g_fr[(r0 + f)*NFFT + n] = xv * g_win[n];
  }
}

// ------------------------- CT stft + GL update (R8 structure) ----------------
struct StftS {
  float fS[FRB][NFFT];
  struct { float uS[FRB][17][25]; float vS[FRB][17][25]; } fd;
  float Gr[FRB][25][17], Gi[FRB][25][17];
  float c32[32][17], s32[32][17];
};

__global__ __launch_bounds__(256)
void k_stft(){
  __shared__ StftS S;
  const int tid = threadIdx.x;
  const int r0 = blockIdx.x * FRB;

  for (int i = tid; i < 32*17; i += 256){
    int a = i/17, c = i - 17*a;
    S.c32[a][c] = g_c32[a][c]; S.s32[a][c] = g_s32[a][c];
  }
  // reflect-pad gather * window
  for (int i = tid; i < FRB*NFFT; i += 256){
    int f = i / NFFT, n = i - f*NFFT;
    int r = r0 + f, b = r >> 9, t = r & 511;
    int s = t*200 + n - 400;
    if (s < 0) s = -s;
    else if (s >= LOUT) s = 2*LOUT - 2 - s;
    S.fS[f][n] = g_inv[b*LOUT + s] * g_win[n];
  }
  __syncthreads();

  // fold p <-> 32-p (real input)
  for (int i = tid; i < FRB*17*25; i += 256){
    int f = i / 425, rem = i - f*425;
    int p = rem / 25, q = rem - 25*p;
    float u, v;
    if (p == 0)      { u = S.fS[f][q];       v = 0.f; }
    else if (p == 16){ u = S.fS[f][400 + q]; v = 0.f; }
    else { float a = S.fS[f][25*p + q], cc = S.fS[f][25*(32-p) + q];
           u = a + cc; v = a - cc; }
    S.fd.uS[f][p][q] = u; S.fd.vS[f][p][q] = v;
  }
  __syncthreads();

  // stage F1
  for (int i = tid; i < FRB*25*17; i += 256){
    int f = i / 425, rem = i - f*425;
    int q = rem / 17, m = rem - 17*q;
    float gr = 0.f, gi = 0.f;
#pragma unroll
    for (int p = 0; p <= 16; p++){
      gr = fmaf(S.fd.uS[f][p][q], S.c32[m][p], gr);
      gi = fmaf(S.fd.vS[f][p][q], S.s32[m][p], gi);
    }
    S.Gr[f][q][m] = gr; S.Gi[f][q][m] = -gi;
  }
  __syncthreads();

  // stage F2 + momentum + phase normalize (tables amortized over FRB frames)
  for (int k = tid; k < NF; k += 256){
    int m = k & 31;
    int mm = (m <= 16) ? m : 32 - m;
    float sg = (m <= 16) ? 1.f : -1.f;
    float xr[FRB], xi[FRB];
#pragma unroll
    for (int f = 0; f < FRB; f++){ xr[f] = 0.f; xi[f] = 0.f; }
#pragma unroll 5
    for (int q = 0; q < 25; q++){
      float cc = g_TFc[q][k], s = g_TFs[q][k];
#pragma unroll
      for (int f = 0; f < FRB; f++){
        float grv = S.Gr[f][q][mm], giv = sg*S.Gi[f][q][mm];
        xr[f] = fmaf(cc, grv, xr[f]); xr[f] = fmaf(s, giv, xr[f]);
        xi[f] = fmaf(cc, giv, xi[f]); xi[f] = fmaf(-s, grv, xi[f]);
      }
    }
#pragma unroll
    for (int f = 0; f < FRB; f++){
      int idx = (r0 + f)*NF + k;
      float nR = xr[f] - 0.49748743718592965f * g_tR[idx];   // 0.99/1.99
      float nI = xi[f] - 0.49748743718592965f * g_tI[idx];
      float d = sqrtf(nR*nR + nI*nI) + 1e-16f;
      g_angR[idx] = nR / d;
      g_angI[idx] = nI / d;
      g_tR[idx] = xr[f]; g_tI[idx] = xi[f];
    }
  }
}

// ------------------------- elementwise kernels -------------------------------
__global__ void k_ola(){
  int i = blockIdx.x*blockDim.x + threadIdx.x;
  if (i >= NB*LOUT) return;
  int b = i / LOUT, l = i - b*LOUT;
  int j = l + 400;
  int tlo = (j >= 600) ? (j-600)/200 : 0;
  int thi = j/200; if (thi > 511) thi = 511;
  float s = 0.f;
  for (int t = tlo; t <= thi; t++)
    s += g_fr[(b*NT + t)*NFFT + (j - 200*t)];
  g_inv[i] = s * g_wsqi[j];
}

__global__ void k_peak(){
  __shared__ float sm[256];
  int b = blockIdx.x;
  float mx = 0.f;
  for (int l = threadIdx.x; l < LOUT; l += 256)
    mx = fmaxf(mx, fabsf(g_inv[b*LOUT + l]));
  sm[threadIdx.x] = mx;
  __syncthreads();
  for (int s = 128; s > 0; s >>= 1){
    if (threadIdx.x < s) sm[threadIdx.x] = fmaxf(sm[threadIdx.x], sm[threadIdx.x + s]);
    __syncthreads();
  }
  if (threadIdx.x == 0) g_peak[b] = 0.98855309465693896f / sm[0];  // 10^(-0.1/20)
}

__global__ void k_scale(float* __restrict__ out){
  int i = blockIdx.x*blockDim.x + threadIdx.x;
  if (i >= NB*LOUT) return;
  out[i] = g_inv[i] * g_peak[i / LOUT];
}

// ------------------------- host driver ---------------------------------------
extern "C" void kernel_launch(void* const* d_in, const int* in_sizes, int n_in,
                              void* d_out, int out_size){
  const float* x = (const float*)d_in[0];
  float* out = (float*)d_out;

  static int attr_done = 0;
  if (!attr_done){
    cudaFuncSetAttribute(k_mel50, cudaFuncAttributeMaxDynamicSharedMemorySize,
                         (int)sizeof(MelS));
    cudaFuncSetAttribute(k_istft, cudaFuncAttributePreferredSharedMemoryCarveout,
                         cudaSharedmemCarveoutMaxShared);
    cudaFuncSetAttribute(k_stft,  cudaFuncAttributePreferredSharedMemoryCarveout,
                         cudaSharedmemCarveoutMaxShared);
    attr_done = 1;
  }

  // JAX key derivation: key(1)=(0,1); partitionable split -> child_i = block(key,(0,i))
  unsigned a0,a1,b0,b1,r0,r1,q0,q1;
  tf_block(0u,1u, 0u,0u, a0,a1);   // k1  (inverse mel spec0)
  tf_block(0u,1u, 0u,1u, b0,b1);   // k2  (griffin-lim)
  tf_block(b0,b1, 0u,0u, r0,r1);   // kr  (angle real)
  tf_block(b0,b1, 0u,1u, q0,q1);   // ki  (angle imag)

  k_setup1<<<(NF*NMEL + 255)/256, 256>>>();
  k_setup2<<<(SET2_TOT + 255)/256, 256>>>();
  k_init<<<(NTOT + 255)/256, 256>>>(a0,a1,r0,r1,q0,q1);

  // InverseMelScale: all 50 SGD+momentum iterations in ONE launch
  k_mel50<<<ROWS/MROWS, 256, sizeof(MelS)>>>(x);

  // Griffin-Lim: 30 iterations (R8 shape: grid=1024, one chunk per block)
  for (int it = 0; it < 30; it++){
    k_istft<<<ROWS/FRB, 256>>>();
    k_ola<<<(NB*LOUT + 255)/256, 256>>>();
    k_stft<<<ROWS/FRB, 256>>>();
  }

  // final istft with converged phases
  k_istft<<<ROWS/FRB, 256>>>();
  k_ola<<<(NB*LOUT + 255)/256, 256>>>();

  // normalize to -0.1 dB peak
  k_peak <<<NB, 256>>>();
  k_scale<<<(NB*LOUT + 255)/256, 256>>>(out);
}

// round 12
// speedup vs baseline: 1.2513x; 1.0510x over previous
#include <cuda_runtime.h>
#include <stdint.h>

#define NB    8
#define NMEL  80
#define NT    512
#define NF    401
#define NFFT  800
#define LOUT  102200
#define LPAD  103000
#define ROWS  4096
#define NTOT  1642496     /* ROWS*NF  */
#define FRTOT 3276800     /* ROWS*NFFT */
#define FRB   4           /* frames per block in CT kernels */
#define KPAD  416         /* padded k extent: 32*13 */
#define BW    24          /* mel filter band width (max ~22 nonzeros) */
#define MROWS 8           /* rows per block in mega-mel */

// ------------------------- device scratch (no allocs) ------------------------
__device__ float  g_fb  [NF*NMEL];
__device__ float  g_fbT [NMEL*NF];
__device__ float  g_win [NFFT];
__device__ double g_twcD[NFFT];
__device__ double g_twsD[NFFT];
__device__ float  g_wsqi[LPAD];
__device__ float  g_TIc [25][KPAD];  // (w_k/800)cos(2pi k q/800), 0 for k>=401
__device__ float  g_TIs [25][KPAD];
__device__ float  g_TFc [25][KPAD];  // cos(2pi k q/800)
__device__ float  g_TFs [25][KPAD];
__device__ float  g_c32 [32][17];
__device__ float  g_s32 [32][17];
__device__ int    g_klo [NMEL];      // first nonzero k of fb column m
__device__ float  g_fbc [NMEL][BW];  // fb[klo+j][m], zero-padded
__device__ int    g_ms  [NF];        // first nonzero m of fbT column f
__device__ float  g_fbv [NF][4];     // fbT[ms+j][f], zero-padded
__device__ float  g_spec[NTOT];
__device__ float  g_mag [NTOT];
__device__ float  g_angR[NTOT];
__device__ float  g_angI[NTOT];
__device__ float  g_tR  [NTOT];
__device__ float  g_tI  [NTOT];
__device__ float  g_fr  [FRTOT];
__device__ float  g_inv [NB*LOUT];
__device__ float  g_peak[NB];

// ------------------------- threefry-2x32 (JAX schedule) ----------------------
__host__ __device__ inline void tf_block(unsigned k0, unsigned k1,
                                         unsigned c0, unsigned c1,
                                         unsigned &o0, unsigned &o1){
  unsigned ks2 = k0 ^ k1 ^ 0x1BD11BDAu;
  unsigned x0 = c0 + k0, x1 = c1 + k1;
#define TFR(r) { x0 += x1; x1 = (x1 << (r)) | (x1 >> (32 - (r))); x1 ^= x0; }
  TFR(13) TFR(15) TFR(26) TFR(6)  x0 += k1;  x1 += ks2 + 1u;
  TFR(17) TFR(29) TFR(16) TFR(24) x0 += ks2; x1 += k0 + 2u;
  TFR(13) TFR(15) TFR(26) TFR(6)  x0 += k0;  x1 += k1 + 3u;
  TFR(17) TFR(29) TFR(16) TFR(24) x0 += k1;  x1 += ks2 + 4u;
  TFR(13) TFR(15) TFR(26) TFR(6)  x0 += ks2; x1 += k0 + 5u;
#undef TFR
  o0 = x0; o1 = x1;
}

__device__ __forceinline__ float u01(unsigned bits){
  return __uint_as_float((bits >> 9) | 0x3f800000u) - 1.0f;
}

// ------------------------- setup kernels ------------------------------------
__global__ void k_setup1(){
  int i = blockIdx.x*blockDim.x + threadIdx.x;
  if (i < NFFT){
    g_win[i]  = (float)(0.5 - 0.5*cospi((double)i/400.0));
    g_twcD[i] = cospi((double)i/400.0);
    g_twsD[i] = sinpi((double)i/400.0);
  }
  if (i < NF*NMEL){
    int f = i / NMEL, m = i - f*NMEL;
    double freq = 10.0 * f;
    double mmax = 2595.0 * log10(1.0 + 4000.0/700.0);
    double p0 = 700.0*(pow(10.0, (mmax*(double)(m  )/81.0)/2595.0) - 1.0);
    double p1 = 700.0*(pow(10.0, (mmax*(double)(m+1)/81.0)/2595.0) - 1.0);
    double p2 = 700.0*(pow(10.0, (mmax*(double)(m+2)/81.0)/2595.0) - 1.0);
    double down = (freq - p0) / (p1 - p0);
    double up   = (p2 - freq) / (p2 - p1);
    double v = fmax(0.0, fmin(down, up));
    g_fb [f*NMEL + m] = (float)v;
    g_fbT[m*NF  + f] = (float)v;
  }
}

#define SET2_TOT (LPAD + 25*KPAD + 32*17 + NMEL + NF)
__global__ void k_setup2(){
  int i = blockIdx.x*blockDim.x + threadIdx.x;
  if (i < LPAD){
    int j = i;
    int tlo = (j >= 600) ? (j-600)/200 : 0;
    int thi = j/200; if (thi > 511) thi = 511;
    double s = 0.0;
    for (int t = tlo; t <= thi; t++){
      double w = (double)g_win[j - 200*t];
      s += w*w;
    }
    s = fmax(s, 1e-11);
    g_wsqi[j] = (float)(1.0 / s);
    return;
  }
  int ib = i - LPAD;
  if (ib < 25*KPAD){
    int q = ib / KPAD, k = ib - q*KPAD;
    if (k < NF){
      int r = (k*q) % 800;
      double c = g_twcD[r], s = g_twsD[r];
      double w = (k == 0 || k == 400) ? 1.0 : 2.0;
      g_TIc[q][k] = (float)(w/800.0 * c);
      g_TIs[q][k] = (float)(w/800.0 * s);
      g_TFc[q][k] = (float)c;
      g_TFs[q][k] = (float)s;
    } else {
      g_TIc[q][k] = 0.f; g_TIs[q][k] = 0.f;
      g_TFc[q][k] = 0.f; g_TFs[q][k] = 0.f;
    }
    return;
  }
  int ic = ib - 25*KPAD;
  if (ic < 32*17){
    int a = ic / 17, b = ic - 17*a;
    int r = (a*b) % 32;
    g_c32[a][b] = (float)cospi((double)r/16.0);
    g_s32[a][b] = (float)sinpi((double)r/16.0);
    return;
  }
  int id = ic - 32*17;
  if (id < NMEL){
    int m = id;
    int klo = 0;
    for (int k = 0; k < NF; k++)
      if (g_fb[k*NMEL + m] > 0.f){ klo = k; break; }
    g_klo[m] = klo;
    for (int j = 0; j < BW; j++){
      int k = klo + j;
      g_fbc[m][j] = (k < NF) ? g_fb[k*NMEL + m] : 0.f;
    }
    return;
  }
  int ie = id - NMEL;
  if (ie < NF){
    int f = ie;
    int ms = 0;
    for (int m = 0; m < NMEL; m++)
      if (g_fbT[m*NF + f] > 0.f){ ms = m; break; }
    g_ms[f] = ms;
    for (int j = 0; j < 4; j++){
      int m = ms + j;
      g_fbv[f][j] = (m < NMEL) ? g_fbT[m*NF + f] : 0.f;
    }
  }
}

// ------------------------- RNG init ------------------------------------------
__global__ void k_init(unsigned a0, unsigned a1, unsigned r0, unsigned r1,
                       unsigned q0, unsigned q1){
  int i = blockIdx.x*blockDim.x + threadIdx.x;
  if (i >= NTOT) return;
  unsigned o0, o1;
  tf_block(a0, a1, 0u, (unsigned)i, o0, o1);
  g_spec[i] = u01(o0 ^ o1);                     // spec0 is (B,T,F) = our layout
  g_tR[i] = 0.f; g_tI[i] = 0.f;
  // angles drawn in (B,F,T) order -> remap flat index
  int b = i / (NT*NF);
  int rem = i - b*(NT*NF);
  int t = rem / NF, f = rem - t*NF;
  unsigned j = (unsigned)(b*(NF*NT) + f*NT + t);
  tf_block(r0, r1, 0u, j, o0, o1); g_angR[i] = u01(o0 ^ o1);
  tf_block(q0, q1, 0u, j, o0, o1); g_angI[i] = u01(o0 ^ o1);
}

// ------------------------- mega mel: all 50 SGD iterations in one launch ----
// R8 thread mapping (1 output/thread) + TRANSPOSED filter tables in smem:
// fbcT[j][m] and fbvT[j][f] give stride-1 (conflict-free) lane access.
// Same float values, same per-output ascending fmaf chains -> bit-identical.
struct MelS {
  float sS[MROWS][440];   // spec rows, zero-padded k>=401
  float vS[MROWS][404];   // velocity
  float dS[MROWS][84];    // diff, zero-padded m>=80
  float xS[MROWS][80];    // mel target (cached)
  float fbcT[BW][80];     // transposed: fbcT[j][m] = fb band tap j of mel m
  float fbvT[4][404];     // transposed: fbvT[j][f] = fbT band tap j of freq f
  int   klo[NMEL];
  int   ms[NF];
};

__global__ __launch_bounds__(256)
void k_mel50(const float* __restrict__ x){
  extern __shared__ char smraw[];
  MelS* S = (MelS*)smraw;
  const int tid = threadIdx.x;
  const int row0 = blockIdx.x * MROWS;

  for (int i = tid; i < MROWS*440; i += 256){
    int r = i / 440, k = i - r*440;
    S->sS[r][k] = (k < NF) ? g_spec[(row0 + r)*NF + k] : 0.f;
  }
  for (int i = tid; i < MROWS*404; i += 256){
    int r = i / 404, k = i - r*404;
    S->vS[r][k] = 0.f;
  }
  for (int i = tid; i < MROWS*84; i += 256){
    int r = i / 84, m = i - r*84;
    if (m >= NMEL) S->dS[r][m] = 0.f;
  }
  for (int i = tid; i < MROWS*NMEL; i += 256){
    int r = i / NMEL, m = i - r*NMEL;
    int row = row0 + r, b = row >> 9, t = row & 511;
    S->xS[r][m] = x[(b*NMEL + m)*NT + t];
  }
  for (int i = tid; i < NMEL*BW; i += 256){
    int m = i / BW, j = i - m*BW;
    S->fbcT[j][m] = g_fbc[m][j];          // transpose on load
  }
  for (int i = tid; i < NF*4; i += 256){
    int f = i >> 2, j = i & 3;
    S->fbvT[j][f] = g_fbv[f][j];          // transpose on load
  }
  for (int i = tid; i < NMEL; i += 256) S->klo[i] = g_klo[i];
  for (int i = tid; i < NF;   i += 256) S->ms[i]  = g_ms[i];
  __syncthreads();

#pragma unroll 1
  for (int it = 0; it < 50; it++){
    // phase A: diff[r][m] = mel_t - sum_k spec*fb (banded, ascending k)
    for (int i = tid; i < MROWS*NMEL; i += 256){
      int r = i / NMEL, m = i - r*NMEL;
      int klo = S->klo[m];
      float acc = 0.f;
#pragma unroll
      for (int j = 0; j < BW; j++)
        acc = fmaf(S->sS[r][klo + j], S->fbcT[j][m], acc);
      S->dS[r][m] = S->xS[r][m] - acc;
    }
    __syncthreads();
    // phase B: g = diff@fbT (banded, ascending m) + momentum + clamp
    for (int i = tid; i < MROWS*NF; i += 256){
      int r = i / NF, f = i - r*NF;
      int ms = S->ms[f];
      float acc = 0.f;
#pragma unroll
      for (int j = 0; j < 4; j++)
        acc = fmaf(S->dS[r][ms + j], S->fbvT[j][f], acc);
      float g = -0.003125f * acc;             // -2/(B*M)
      float v = 0.9f * S->vS[r][f] + g;
      S->vS[r][f] = v;
      S->sS[r][f] = fmaxf(S->sS[r][f] - 0.1f*v, 0.f);
    }
    __syncthreads();
  }

  // epilogue: mag = sqrt(spec)  (k_mag fused)
  for (int i = tid; i < MROWS*NF; i += 256){
    int r = i / NF, k = i - r*NF;
    g_mag[(row0 + r)*NF + k] = sqrtf(S->sS[r][k]);
  }
}

// ------------------------- CT istft (R8 structure, win from global) ----------
struct IstftS {
  union {
    struct { float Pre[FRB][KPAD], Pim[FRB][KPAD]; } a;
    struct { float Aa[FRB][17][25], Bb[FRB][17][25]; } b;
  } u;
  float Hr[FRB][25][32], Hi[FRB][25][32];
  float c32[32][17], s32[32][17];
};

__global__ __launch_bounds__(256)
void k_istft(){
  __shared__ IstftS S;
  const int tid = threadIdx.x;
  const int r0 = blockIdx.x * FRB;

  for (int i = tid; i < 32*17; i += 256){
    int a = i/17, b = i - 17*a;
    S.c32[a][b] = g_c32[a][b]; S.s32[a][b] = g_s32[a][b];
  }
  for (int i = tid; i < FRB*KPAD; i += 256){
    int f = i / KPAD, k = i - f*KPAD;
    if (k < NF){
      int idx = (r0 + f)*NF + k;
      float m = g_mag[idx];
      S.u.a.Pre[f][k] = m * g_angR[idx];
      S.u.a.Pim[f][k] = m * g_angI[idx];
    } else { S.u.a.Pre[f][k] = 0.f; S.u.a.Pim[f][k] = 0.f; }
  }
  __syncthreads();

  // stage I1: H[q][m] = sum_{k==m mod 32} T[q][k]*P[k]  (k ascending)
  for (int i = tid; i < 25*32; i += 256){
    int q = i >> 5, m = i & 31;
    float hr[FRB], hi[FRB];
#pragma unroll
    for (int f = 0; f < FRB; f++){ hr[f] = 0.f; hi[f] = 0.f; }
#pragma unroll
    for (int j = 0; j < 13; j++){
      int k = m + (j << 5);
      float tr = g_TIc[q][k], ti = g_TIs[q][k];
#pragma unroll
      for (int f = 0; f < FRB; f++){
        float pr = S.u.a.Pre[f][k], pi = S.u.a.Pim[f][k];
        hr[f] = fmaf(tr, pr, hr[f]); hr[f] = fmaf(-ti, pi, hr[f]);
        hi[f] = fmaf(tr, pi, hi[f]); hi[f] = fmaf( ti, pr, hi[f]);
      }
    }
#pragma unroll
    for (int f = 0; f < FRB; f++){
      S.Hr[f][q][m] = hr[f]; S.Hi[f][q][m] = hi[f];
    }
  }
  __syncthreads();

  // fold m <-> 32-m (real extraction); overlays dead Pre/Pim
  for (int i = tid; i < FRB*17*25; i += 256){
    int f = i / 425, rem = i - f*425;
    int m = rem / 25, q = rem - 25*m;
    float a, b;
    if (m == 0)      { a = S.Hr[f][q][0];  b = 0.f; }
    else if (m == 16){ a = S.Hr[f][q][16]; b = 0.f; }
    else { a = S.Hr[f][q][m] + S.Hr[f][q][32-m];
           b = S.Hi[f][q][32-m] - S.Hi[f][q][m]; }
    S.u.b.Aa[f][m][q] = a; S.u.b.Bb[f][m][q] = b;
  }
  __syncthreads();

  // stage I2 + window (win via L1-cached global read)
  for (int i = tid; i < FRB*NFFT; i += 256){
    int f = i / NFFT, n = i - f*NFFT;
    int p = n / 25, q = n - 25*p;
    float xv = 0.f;
#pragma unroll
    for (int m = 0; m <= 16; m++){
      xv = fmaf(S.u.b.Aa[f][m][q], S.c32[p][m], xv);
      xv = fmaf(S.u.b.Bb[f][m][q], S.s32[p][m], xv);
    }
    g_fr[(r0 + f)*NFFT + n] = xv * g_win[n];
  }
}

// ------------------------- CT stft + GL update (R8 structure) ----------------
struct StftS {
  float fS[FRB][NFFT];
  struct { float uS[FRB][17][25]; float vS[FRB][17][25]; } fd;
  float Gr[FRB][25][17], Gi[FRB][25][17];
  float c32[32][17], s32[32][17];
};

__global__ __launch_bounds__(256)
void k_stft(){
  __shared__ StftS S;
  const int tid = threadIdx.x;
  const int r0 = blockIdx.x * FRB;

  for (int i = tid; i < 32*17; i += 256){
    int a = i/17, c = i - 17*a;
    S.c32[a][c] = g_c32[a][c]; S.s32[a][c] = g_s32[a][c];
  }
  // reflect-pad gather * window
  for (int i = tid; i < FRB*NFFT; i += 256){
    int f = i / NFFT, n = i - f*NFFT;
    int r = r0 + f, b = r >> 9, t = r & 511;
    int s = t*200 + n - 400;
    if (s < 0) s = -s;
    else if (s >= LOUT) s = 2*LOUT - 2 - s;
    S.fS[f][n] = g_inv[b*LOUT + s] * g_win[n];
  }
  __syncthreads();

  // fold p <-> 32-p (real input)
  for (int i = tid; i < FRB*17*25; i += 256){
    int f = i / 425, rem = i - f*425;
    int p = rem / 25, q = rem - 25*p;
    float u, v;
    if (p == 0)      { u = S.fS[f][q];       v = 0.f; }
    else if (p == 16){ u = S.fS[f][400 + q]; v = 0.f; }
    else { float a = S.fS[f][25*p + q], cc = S.fS[f][25*(32-p) + q];
           u = a + cc; v = a - cc; }
    S.fd.uS[f][p][q] = u; S.fd.vS[f][p][q] = v;
  }
  __syncthreads();

  // stage F1
  for (int i = tid; i < FRB*25*17; i += 256){
    int f = i / 425, rem = i - f*425;
    int q = rem / 17, m = rem - 17*q;
    float gr = 0.f, gi = 0.f;
#pragma unroll
    for (int p = 0; p <= 16; p++){
      gr = fmaf(S.fd.uS[f][p][q], S.c32[m][p], gr);
      gi = fmaf(S.fd.vS[f][p][q], S.s32[m][p], gi);
    }
    S.Gr[f][q][m] = gr; S.Gi[f][q][m] = -gi;
  }
  __syncthreads();

  // stage F2 + momentum + phase normalize (tables amortized over FRB frames)
  for (int k = tid; k < NF; k += 256){
    int m = k & 31;
    int mm = (m <= 16) ? m : 32 - m;
    float sg = (m <= 16) ? 1.f : -1.f;
    float xr[FRB], xi[FRB];
#pragma unroll
    for (int f = 0; f < FRB; f++){ xr[f] = 0.f; xi[f] = 0.f; }
#pragma unroll 5
    for (int q = 0; q < 25; q++){
      float cc = g_TFc[q][k], s = g_TFs[q][k];
#pragma unroll
      for (int f = 0; f < FRB; f++){
        float grv = S.Gr[f][q][mm], giv = sg*S.Gi[f][q][mm];
        xr[f] = fmaf(cc, grv, xr[f]); xr[f] = fmaf(s, giv, xr[f]);
        xi[f] = fmaf(cc, giv, xi[f]); xi[f] = fmaf(-s, grv, xi[f]);
      }
    }
#pragma unroll
    for (int f = 0; f < FRB; f++){
      int idx = (r0 + f)*NF + k;
      float nR = xr[f] - 0.49748743718592965f * g_tR[idx];   // 0.99/1.99
      float nI = xi[f] - 0.49748743718592965f * g_tI[idx];
      float d = sqrtf(nR*nR + nI*nI) + 1e-16f;
      g_angR[idx] = nR / d;
      g_angI[idx] = nI / d;
      g_tR[idx] = xr[f]; g_tI[idx] = xi[f];
    }
  }
}

// ------------------------- elementwise kernels -------------------------------
__global__ void k_ola(){
  int i = blockIdx.x*blockDim.x + threadIdx.x;
  if (i >= NB*LOUT) return;
  int b = i / LOUT, l = i - b*LOUT;
  int j = l + 400;
  int tlo = (j >= 600) ? (j-600)/200 : 0;
  int thi = j/200; if (thi > 511) thi = 511;
  float s = 0.f;
  for (int t = tlo; t <= thi; t++)
    s += g_fr[(b*NT + t)*NFFT + (j - 200*t)];
  g_inv[i] = s * g_wsqi[j];
}

__global__ void k_peak(){
  __shared__ float sm[256];
  int b = blockIdx.x;
  float mx = 0.f;
  for (int l = threadIdx.x; l < LOUT; l += 256)
    mx = fmaxf(mx, fabsf(g_inv[b*LOUT + l]));
  sm[threadIdx.x] = mx;
  __syncthreads();
  for (int s = 128; s > 0; s >>= 1){
    if (threadIdx.x < s) sm[threadIdx.x] = fmaxf(sm[threadIdx.x], sm[threadIdx.x + s]);
    __syncthreads();
  }
  if (threadIdx.x == 0) g_peak[b] = 0.98855309465693896f / sm[0];  // 10^(-0.1/20)
}

__global__ void k_scale(float* __restrict__ out){
  int i = blockIdx.x*blockDim.x + threadIdx.x;
  if (i >= NB*LOUT) return;
  out[i] = g_inv[i] * g_peak[i / LOUT];
}

// ------------------------- host driver ---------------------------------------
extern "C" void kernel_launch(void* const* d_in, const int* in_sizes, int n_in,
                              void* d_out, int out_size){
  const float* x = (const float*)d_in[0];
  float* out = (float*)d_out;

  static int attr_done = 0;
  if (!attr_done){
    cudaFuncSetAttribute(k_mel50, cudaFuncAttributeMaxDynamicSharedMemorySize,
                         (int)sizeof(MelS));
    cudaFuncSetAttribute(k_istft, cudaFuncAttributePreferredSharedMemoryCarveout,
                         cudaSharedmemCarveoutMaxShared);
    cudaFuncSetAttribute(k_stft,  cudaFuncAttributePreferredSharedMemoryCarveout,
                         cudaSharedmemCarveoutMaxShared);
    attr_done = 1;
  }

  // JAX key derivation: key(1)=(0,1); partitionable split -> child_i = block(key,(0,i))
  unsigned a0,a1,b0,b1,r0,r1,q0,q1;
  tf_block(0u,1u, 0u,0u, a0,a1);   // k1  (inverse mel spec0)
  tf_block(0u,1u, 0u,1u, b0,b1);   // k2  (griffin-lim)
  tf_block(b0,b1, 0u,0u, r0,r1);   // kr  (angle real)
  tf_block(b0,b1, 0u,1u, q0,q1);   // ki  (angle imag)

  k_setup1<<<(NF*NMEL + 255)/256, 256>>>();
  k_setup2<<<(SET2_TOT + 255)/256, 256>>>();
  k_init<<<(NTOT + 255)/256, 256>>>(a0,a1,r0,r1,q0,q1);

  // InverseMelScale: all 50 SGD+momentum iterations in ONE launch
  k_mel50<<<ROWS/MROWS, 256, sizeof(MelS)>>>(x);

  // Griffin-Lim: 30 iterations (R8 shape: grid=1024, one chunk per block)
  for (int it = 0; it < 30; it++){
    k_istft<<<ROWS/FRB, 256>>>();
    k_ola<<<(NB*LOUT + 255)/256, 256>>>();
    k_stft<<<ROWS/FRB, 256>>>();
  }

  // final istft with converged phases
  k_istft<<<ROWS/FRB, 256>>>();
  k_ola<<<(NB*LOUT + 255)/256, 256>>>();

  // normalize to -0.1 dB peak
  k_peak <<<NB, 256>>>();
  k_scale<<<(NB*LOUT + 255)/256, 256>>>(out);
}

// round 13
// speedup vs baseline: 1.3195x; 1.0545x over previous
#include <cuda_runtime.h>
#include <stdint.h>

#define NB    8
#define NMEL  80
#define NT    512
#define NF    401
#define NFFT  800
#define LOUT  102200
#define LPAD  103000
#define ROWS  4096
#define NTOT  1642496     /* ROWS*NF  */
#define FRTOT 3276800     /* ROWS*NFFT */
#define FRB   4           /* frames per block in CT kernels */
#define KPAD  416         /* padded k extent: 32*13 */
#define BW    24          /* mel filter band width (max ~22 nonzeros) */
#define MROWS 8           /* rows per block in mega-mel */

// ------------------------- device scratch (no allocs) ------------------------
__device__ float  g_fb  [NF*NMEL];
__device__ float  g_fbT [NMEL*NF];
__device__ float  g_win [NFFT];
__device__ double g_twcD[NFFT];
__device__ double g_twsD[NFFT];
__device__ float  g_wsqi[LPAD];
__device__ float2 g_TI  [25][KPAD];  // (w/800)·(cos,sin)(2pi k q/800), 0 pad
__device__ float2 g_TF  [25][KPAD];  // (cos,sin)(2pi k q/800), 0 pad
__device__ float2 g_cs32[32][17];    // (cos,sin)(2pi a b/32)
__device__ int    g_klo [NMEL];      // first nonzero k of fb column m
__device__ float  g_fbc [NMEL][BW];  // fb[klo+j][m], zero-padded
__device__ int    g_ms  [NF];        // first nonzero m of fbT column f
__device__ float  g_fbv [NF][4];     // fbT[ms+j][f], zero-padded
__device__ float  g_spec[NTOT];
__device__ float  g_mag [NTOT];
__device__ float2 g_ang [NTOT];      // (angR, angI)
__device__ float2 g_t   [NTOT];      // (tR, tI)
__device__ float  g_fr  [FRTOT];
__device__ float  g_inv [NB*LOUT];
__device__ float  g_peak[NB];

// ------------------------- threefry-2x32 (JAX schedule) ----------------------
__host__ __device__ inline void tf_block(unsigned k0, unsigned k1,
                                         unsigned c0, unsigned c1,
                                         unsigned &o0, unsigned &o1){
  unsigned ks2 = k0 ^ k1 ^ 0x1BD11BDAu;
  unsigned x0 = c0 + k0, x1 = c1 + k1;
#define TFR(r) { x0 += x1; x1 = (x1 << (r)) | (x1 >> (32 - (r))); x1 ^= x0; }
  TFR(13) TFR(15) TFR(26) TFR(6)  x0 += k1;  x1 += ks2 + 1u;
  TFR(17) TFR(29) TFR(16) TFR(24) x0 += ks2; x1 += k0 + 2u;
  TFR(13) TFR(15) TFR(26) TFR(6)  x0 += k0;  x1 += k1 + 3u;
  TFR(17) TFR(29) TFR(16) TFR(24) x0 += k1;  x1 += ks2 + 4u;
  TFR(13) TFR(15) TFR(26) TFR(6)  x0 += ks2; x1 += k0 + 5u;
#undef TFR
  o0 = x0; o1 = x1;
}

__device__ __forceinline__ float u01(unsigned bits){
  return __uint_as_float((bits >> 9) | 0x3f800000u) - 1.0f;
}

// ------------------------- setup kernels ------------------------------------
__global__ void k_setup1(){
  int i = blockIdx.x*blockDim.x + threadIdx.x;
  if (i < NFFT){
    g_win[i]  = (float)(0.5 - 0.5*cospi((double)i/400.0));
    g_twcD[i] = cospi((double)i/400.0);
    g_twsD[i] = sinpi((double)i/400.0);
  }
  if (i < NF*NMEL){
    int f = i / NMEL, m = i - f*NMEL;
    double freq = 10.0 * f;
    double mmax = 2595.0 * log10(1.0 + 4000.0/700.0);
    double p0 = 700.0*(pow(10.0, (mmax*(double)(m  )/81.0)/2595.0) - 1.0);
    double p1 = 700.0*(pow(10.0, (mmax*(double)(m+1)/81.0)/2595.0) - 1.0);
    double p2 = 700.0*(pow(10.0, (mmax*(double)(m+2)/81.0)/2595.0) - 1.0);
    double down = (freq - p0) / (p1 - p0);
    double up   = (p2 - freq) / (p2 - p1);
    double v = fmax(0.0, fmin(down, up));
    g_fb [f*NMEL + m] = (float)v;
    g_fbT[m*NF  + f] = (float)v;
  }
}

#define SET2_TOT (LPAD + 25*KPAD + 32*17 + NMEL + NF)
__global__ void k_setup2(){
  int i = blockIdx.x*blockDim.x + threadIdx.x;
  if (i < LPAD){
    int j = i;
    int tlo = (j >= 600) ? (j-600)/200 : 0;
    int thi = j/200; if (thi > 511) thi = 511;
    double s = 0.0;
    for (int t = tlo; t <= thi; t++){
      double w = (double)g_win[j - 200*t];
      s += w*w;
    }
    s = fmax(s, 1e-11);
    g_wsqi[j] = (float)(1.0 / s);
    return;
  }
  int ib = i - LPAD;
  if (ib < 25*KPAD){
    int q = ib / KPAD, k = ib - q*KPAD;
    if (k < NF){
      int r = (k*q) % 800;
      double c = g_twcD[r], s = g_twsD[r];
      double w = (k == 0 || k == 400) ? 1.0 : 2.0;
      g_TI[q][k] = make_float2((float)(w/800.0 * c), (float)(w/800.0 * s));
      g_TF[q][k] = make_float2((float)c, (float)s);
    } else {
      g_TI[q][k] = make_float2(0.f, 0.f);
      g_TF[q][k] = make_float2(0.f, 0.f);
    }
    return;
  }
  int ic = ib - 25*KPAD;
  if (ic < 32*17){
    int a = ic / 17, b = ic - 17*a;
    int r = (a*b) % 32;
    g_cs32[a][b] = make_float2((float)cospi((double)r/16.0),
                               (float)sinpi((double)r/16.0));
    return;
  }
  int id = ic - 32*17;
  if (id < NMEL){
    int m = id;
    int klo = 0;
    for (int k = 0; k < NF; k++)
      if (g_fb[k*NMEL + m] > 0.f){ klo = k; break; }
    g_klo[m] = klo;
    for (int j = 0; j < BW; j++){
      int k = klo + j;
      g_fbc[m][j] = (k < NF) ? g_fb[k*NMEL + m] : 0.f;
    }
    return;
  }
  int ie = id - NMEL;
  if (ie < NF){
    int f = ie;
    int ms = 0;
    for (int m = 0; m < NMEL; m++)
      if (g_fbT[m*NF + f] > 0.f){ ms = m; break; }
    g_ms[f] = ms;
    for (int j = 0; j < 4; j++){
      int m = ms + j;
      g_fbv[f][j] = (m < NMEL) ? g_fbT[m*NF + f] : 0.f;
    }
  }
}

// ------------------------- RNG init ------------------------------------------
__global__ void k_init(unsigned a0, unsigned a1, unsigned r0, unsigned r1,
                       unsigned q0, unsigned q1){
  int i = blockIdx.x*blockDim.x + threadIdx.x;
  if (i >= NTOT) return;
  unsigned o0, o1;
  tf_block(a0, a1, 0u, (unsigned)i, o0, o1);
  g_spec[i] = u01(o0 ^ o1);                     // spec0 is (B,T,F) = our layout
  g_t[i] = make_float2(0.f, 0.f);
  // angles drawn in (B,F,T) order -> remap flat index
  int b = i / (NT*NF);
  int rem = i - b*(NT*NF);
  int t = rem / NF, f = rem - t*NF;
  unsigned j = (unsigned)(b*(NF*NT) + f*NT + t);
  unsigned p0, p1;
  tf_block(r0, r1, 0u, j, o0, o1);
  tf_block(q0, q1, 0u, j, p0, p1);
  g_ang[i] = make_float2(u01(o0 ^ o1), u01(p0 ^ p1));
}

// ------------------------- mega mel (R12: transposed tables) -----------------
struct MelS {
  float sS[MROWS][440];   // spec rows, zero-padded k>=401
  float vS[MROWS][404];   // velocity
  float dS[MROWS][84];    // diff, zero-padded m>=80
  float xS[MROWS][80];    // mel target (cached)
  float fbcT[BW][80];     // transposed: stride-1 lane access
  float fbvT[4][404];
  int   klo[NMEL];
  int   ms[NF];
};

__global__ __launch_bounds__(256)
void k_mel50(const float* __restrict__ x){
  extern __shared__ char smraw[];
  MelS* S = (MelS*)smraw;
  const int tid = threadIdx.x;
  const int row0 = blockIdx.x * MROWS;

  for (int i = tid; i < MROWS*440; i += 256){
    int r = i / 440, k = i - r*440;
    S->sS[r][k] = (k < NF) ? g_spec[(row0 + r)*NF + k] : 0.f;
  }
  for (int i = tid; i < MROWS*404; i += 256){
    int r = i / 404, k = i - r*404;
    S->vS[r][k] = 0.f;
  }
  for (int i = tid; i < MROWS*84; i += 256){
    int r = i / 84, m = i - r*84;
    if (m >= NMEL) S->dS[r][m] = 0.f;
  }
  for (int i = tid; i < MROWS*NMEL; i += 256){
    int r = i / NMEL, m = i - r*NMEL;
    int row = row0 + r, b = row >> 9, t = row & 511;
    S->xS[r][m] = x[(b*NMEL + m)*NT + t];
  }
  for (int i = tid; i < NMEL*BW; i += 256){
    int m = i / BW, j = i - m*BW;
    S->fbcT[j][m] = g_fbc[m][j];
  }
  for (int i = tid; i < NF*4; i += 256){
    int f = i >> 2, j = i & 3;
    S->fbvT[j][f] = g_fbv[f][j];
  }
  for (int i = tid; i < NMEL; i += 256) S->klo[i] = g_klo[i];
  for (int i = tid; i < NF;   i += 256) S->ms[i]  = g_ms[i];
  __syncthreads();

#pragma unroll 1
  for (int it = 0; it < 50; it++){
    for (int i = tid; i < MROWS*NMEL; i += 256){
      int r = i / NMEL, m = i - r*NMEL;
      int klo = S->klo[m];
      float acc = 0.f;
#pragma unroll
      for (int j = 0; j < BW; j++)
        acc = fmaf(S->sS[r][klo + j], S->fbcT[j][m], acc);
      S->dS[r][m] = S->xS[r][m] - acc;
    }
    __syncthreads();
    for (int i = tid; i < MROWS*NF; i += 256){
      int r = i / NF, f = i - r*NF;
      int ms = S->ms[f];
      float acc = 0.f;
#pragma unroll
      for (int j = 0; j < 4; j++)
        acc = fmaf(S->dS[r][ms + j], S->fbvT[j][f], acc);
      float g = -0.003125f * acc;             // -2/(B*M)
      float v = 0.9f * S->vS[r][f] + g;
      S->vS[r][f] = v;
      S->sS[r][f] = fmaxf(S->sS[r][f] - 0.1f*v, 0.f);
    }
    __syncthreads();
  }

  for (int i = tid; i < MROWS*NF; i += 256){
    int r = i / NF, k = i - r*NF;
    g_mag[(row0 + r)*NF + k] = sqrtf(S->sS[r][k]);
  }
}

// ------------------------- CT istft (float2-paired operands) -----------------
struct IstftS {
  union {
    float2 P [FRB][KPAD];          // (Pre, Pim)   13.3 KB
    float2 AB[FRB][17][25];        // (Aa, Bb)     13.6 KB
  } u;
  float2 H [FRB][25][32];          // (Hr, Hi)     25.6 KB
  float2 cs[32][17];               // (c32, s32)    4.3 KB
};

__global__ __launch_bounds__(256)
void k_istft(){
  __shared__ IstftS S;
  const int tid = threadIdx.x;
  const int r0 = blockIdx.x * FRB;

  for (int i = tid; i < 32*17; i += 256){
    int a = i/17, b = i - 17*a;
    S.cs[a][b] = g_cs32[a][b];
  }
  for (int i = tid; i < FRB*KPAD; i += 256){
    int f = i / KPAD, k = i - f*KPAD;
    if (k < NF){
      int idx = (r0 + f)*NF + k;
      float  m = g_mag[idx];
      float2 a = g_ang[idx];
      S.u.P[f][k] = make_float2(m * a.x, m * a.y);
    } else S.u.P[f][k] = make_float2(0.f, 0.f);
  }
  __syncthreads();

  // stage I1: H[q][m] = sum_{k==m mod 32} T[q][k]*P[k]  (k ascending)
  for (int i = tid; i < 25*32; i += 256){
    int q = i >> 5, m = i & 31;
    float hr[FRB], hi[FRB];
#pragma unroll
    for (int f = 0; f < FRB; f++){ hr[f] = 0.f; hi[f] = 0.f; }
#pragma unroll
    for (int j = 0; j < 13; j++){
      int k = m + (j << 5);
      float2 t = g_TI[q][k];
#pragma unroll
      for (int f = 0; f < FRB; f++){
        float2 p = S.u.P[f][k];
        hr[f] = fmaf(t.x, p.x, hr[f]); hr[f] = fmaf(-t.y, p.y, hr[f]);
        hi[f] = fmaf(t.x, p.y, hi[f]); hi[f] = fmaf( t.y, p.x, hi[f]);
      }
    }
#pragma unroll
    for (int f = 0; f < FRB; f++)
      S.H[f][q][m] = make_float2(hr[f], hi[f]);
  }
  __syncthreads();

  // fold m <-> 32-m (real extraction); overlays dead P
  for (int i = tid; i < FRB*17*25; i += 256){
    int f = i / 425, rem = i - f*425;
    int m = rem / 25, q = rem - 25*m;
    float a, b;
    if (m == 0)      { a = S.H[f][q][0].x;  b = 0.f; }
    else if (m == 16){ a = S.H[f][q][16].x; b = 0.f; }
    else {
      float2 h0 = S.H[f][q][m], h1 = S.H[f][q][32-m];
      a = h0.x + h1.x;
      b = h1.y - h0.y;
    }
    S.u.AB[f][m][q] = make_float2(a, b);
  }
  __syncthreads();

  // stage I2 + window (win via L1-cached global)
  for (int i = tid; i < FRB*NFFT; i += 256){
    int f = i / NFFT, n = i - f*NFFT;
    int p = n / 25, q = n - 25*p;
    float xv = 0.f;
#pragma unroll
    for (int m = 0; m <= 16; m++){
      float2 ab = S.u.AB[f][m][q];
      float2 cs = S.cs[p][m];
      xv = fmaf(ab.x, cs.x, xv);
      xv = fmaf(ab.y, cs.y, xv);
    }
    g_fr[(r0 + f)*NFFT + n] = xv * g_win[n];
  }
}

// ------------------------- CT stft + GL update (float2-paired) ---------------
struct StftS {
  float  fS[FRB][NFFT];            // 12.8 KB
  float2 uv[FRB][17][25];          // (u, v)       13.6 KB
  float2 G [FRB][25][17];          // (Gr, -gi)    13.6 KB
  float2 cs[32][17];               //               4.3 KB
};

__global__ __launch_bounds__(256)
void k_stft(){
  __shared__ StftS S;
  const int tid = threadIdx.x;
  const int r0 = blockIdx.x * FRB;

  for (int i = tid; i < 32*17; i += 256){
    int a = i/17, c = i - 17*a;
    S.cs[a][c] = g_cs32[a][c];
  }
  // reflect-pad gather * window
  for (int i = tid; i < FRB*NFFT; i += 256){
    int f = i / NFFT, n = i - f*NFFT;
    int r = r0 + f, b = r >> 9, t = r & 511;
    int s = t*200 + n - 400;
    if (s < 0) s = -s;
    else if (s >= LOUT) s = 2*LOUT - 2 - s;
    S.fS[f][n] = g_inv[b*LOUT + s] * g_win[n];
  }
  __syncthreads();

  // fold p <-> 32-p (real input)
  for (int i = tid; i < FRB*17*25; i += 256){
    int f = i / 425, rem = i - f*425;
    int p = rem / 25, q = rem - 25*p;
    float u, v;
    if (p == 0)      { u = S.fS[f][q];       v = 0.f; }
    else if (p == 16){ u = S.fS[f][400 + q]; v = 0.f; }
    else { float a = S.fS[f][25*p + q], cc = S.fS[f][25*(32-p) + q];
           u = a + cc; v = a - cc; }
    S.uv[f][p][q] = make_float2(u, v);
  }
  __syncthreads();

  // stage F1  (c32 symmetric: cs[m][p] == cs[p][m] values)
  for (int i = tid; i < FRB*25*17; i += 256){
    int f = i / 425, rem = i - f*425;
    int q = rem / 17, m = rem - 17*q;
    float gr = 0.f, gi = 0.f;
#pragma unroll
    for (int p = 0; p <= 16; p++){
      float2 uv = S.uv[f][p][q];
      float2 cs = S.cs[m][p];
      gr = fmaf(uv.x, cs.x, gr);
      gi = fmaf(uv.y, cs.y, gi);
    }
    S.G[f][q][m] = make_float2(gr, -gi);
  }
  __syncthreads();

  // stage F2 + momentum + phase normalize
  for (int k = tid; k < NF; k += 256){
    int m = k & 31;
    int mm = (m <= 16) ? m : 32 - m;
    float sg = (m <= 16) ? 1.f : -1.f;
    float xr[FRB], xi[FRB];
#pragma unroll
    for (int f = 0; f < FRB; f++){ xr[f] = 0.f; xi[f] = 0.f; }
#pragma unroll 5
    for (int q = 0; q < 25; q++){
      float2 t = g_TF[q][k];
#pragma unroll
      for (int f = 0; f < FRB; f++){
        float2 g = S.G[f][q][mm];
        float grv = g.x, giv = sg * g.y;
        xr[f] = fmaf(t.x, grv, xr[f]); xr[f] = fmaf(t.y, giv, xr[f]);
        xi[f] = fmaf(t.x, giv, xi[f]); xi[f] = fmaf(-t.y, grv, xi[f]);
      }
    }
#pragma unroll
    for (int f = 0; f < FRB; f++){
      int idx = (r0 + f)*NF + k;
      float2 tp = g_t[idx];
      float nR = xr[f] - 0.49748743718592965f * tp.x;   // 0.99/1.99
      float nI = xi[f] - 0.49748743718592965f * tp.y;
      float d = sqrtf(nR*nR + nI*nI) + 1e-16f;
      g_ang[idx] = make_float2(nR / d, nI / d);
      g_t[idx]   = make_float2(xr[f], xi[f]);
    }
  }
}

// ------------------------- elementwise kernels -------------------------------
__global__ void k_ola(){
  int i = blockIdx.x*blockDim.x + threadIdx.x;
  if (i >= NB*LOUT) return;
  int b = i / LOUT, l = i - b*LOUT;
  int j = l + 400;
  int tlo = (j >= 600) ? (j-600)/200 : 0;
  int thi = j/200; if (thi > 511) thi = 511;
  float s = 0.f;
  for (int t = tlo; t <= thi; t++)
    s += g_fr[(b*NT + t)*NFFT + (j - 200*t)];
  g_inv[i] = s * g_wsqi[j];
}

__global__ void k_peak(){
  __shared__ float sm[256];
  int b = blockIdx.x;
  float mx = 0.f;
  for (int l = threadIdx.x; l < LOUT; l += 256)
    mx = fmaxf(mx, fabsf(g_inv[b*LOUT + l]));
  sm[threadIdx.x] = mx;
  __syncthreads();
  for (int s = 128; s > 0; s >>= 1){
    if (threadIdx.x < s) sm[threadIdx.x] = fmaxf(sm[threadIdx.x], sm[threadIdx.x + s]);
    __syncthreads();
  }
  if (threadIdx.x == 0) g_peak[b] = 0.98855309465693896f / sm[0];  // 10^(-0.1/20)
}

__global__ void k_scale(float* __restrict__ out){
  int i = blockIdx.x*blockDim.x + threadIdx.x;
  if (i >= NB*LOUT) return;
  out[i] = g_inv[i] * g_peak[i / LOUT];
}

// ------------------------- host driver ---------------------------------------
extern "C" void kernel_launch(void* const* d_in, const int* in_sizes, int n_in,
                              void* d_out, int out_size){
  const float* x = (const float*)d_in[0];
  float* out = (float*)d_out;

  static int attr_done = 0;
  if (!attr_done){
    cudaFuncSetAttribute(k_mel50, cudaFuncAttributeMaxDynamicSharedMemorySize,
                         (int)sizeof(MelS));
    cudaFuncSetAttribute(k_istft, cudaFuncAttributePreferredSharedMemoryCarveout,
                         cudaSharedmemCarveoutMaxShared);
    cudaFuncSetAttribute(k_stft,  cudaFuncAttributePreferredSharedMemoryCarveout,
                         cudaSharedmemCarveoutMaxShared);
    attr_done = 1;
  }

  // JAX key derivation: key(1)=(0,1); partitionable split -> child_i = block(key,(0,i))
  unsigned a0,a1,b0,b1,r0,r1,q0,q1;
  tf_block(0u,1u, 0u,0u, a0,a1);   // k1  (inverse mel spec0)
  tf_block(0u,1u, 0u,1u, b0,b1);   // k2  (griffin-lim)
  tf_block(b0,b1, 0u,0u, r0,r1);   // kr  (angle real)
  tf_block(b0,b1, 0u,1u, q0,q1);   // ki  (angle imag)

  k_setup1<<<(NF*NMEL + 255)/256, 256>>>();
  k_setup2<<<(SET2_TOT + 255)/256, 256>>>();
  k_init<<<(NTOT + 255)/256, 256>>>(a0,a1,r0,r1,q0,q1);

  // InverseMelScale: all 50 SGD+momentum iterations in ONE launch
  k_mel50<<<ROWS/MROWS, 256, sizeof(MelS)>>>(x);

  // Griffin-Lim: 30 iterations
  for (int it = 0; it < 30; it++){
    k_istft<<<ROWS/FRB, 256>>>();
    k_ola<<<(NB*LOUT + 255)/256, 256>>>();
    k_stft<<<ROWS/FRB, 256>>>();
  }

  // final istft with converged phases
  k_istft<<<ROWS/FRB, 256>>>();
  k_ola<<<(NB*LOUT + 255)/256, 256>>>();

  // normalize to -0.1 dB peak
  k_peak <<<NB, 256>>>();
  k_scale<<<(NB*LOUT + 255)/256, 256>>>(out);
}